// round 6
// baseline (speedup 1.0000x reference)
#include <cuda_runtime.h>
#include <math.h>

// Problem constants
#define BB     16
#define JJ     256
#define KK     384
#define CMETA  6
#define CIN    8      // C_MODEL(1) + C_OBS(1) + C_META(6)
#define WD     32
#define DEPTH  3
#define SS     32     // sample_size
#define JK     (JJ*KK)        // 98304
#define NPTS   (BB*JK)        // 1572864
#define TPB    256
#define PPT    2              // points per thread in k_main
#define PTSBLK (TPB*PPT)      // 512 points per block

// Scratch (device globals; no allocation allowed)
__device__ int   g_fmt;                 // 0=uint8, 1=int32, 2=float32
__device__ int   g_sel[BB][SS];         // selected j indices per batch (unordered set)
__device__ float g_img_sum[BB][WD];     // masked sum of image-branch hidden
__device__ float g_img_cnt[BB];         // masked count

__device__ __forceinline__ bool mask_at(const void* m, int fmt, int i) {
    if (fmt == 0) return ((const unsigned char*)m)[i] != 0;
    if (fmt == 1) return ((const int*)m)[i] != 0;
    return ((const float*)m)[i] != 0.0f;
}

// ---- packed f32x2 helpers (Blackwell FFMA2 — ptxas never auto-fuses) ------
__device__ __forceinline__ unsigned long long pack2(float lo, float hi) {
    unsigned long long r;
    asm("mov.b64 %0, {%1, %2};" : "=l"(r) : "f"(lo), "f"(hi));
    return r;
}
__device__ __forceinline__ void unpack2(unsigned long long v, float& lo, float& hi) {
    asm("mov.b64 {%0, %1}, %2;" : "=f"(lo), "=f"(hi) : "l"(v));
}
__device__ __forceinline__ void fma2(unsigned long long& a,
                                     unsigned long long x, unsigned long long w) {
    asm("fma.rn.f32x2 %0, %1, %2, %3;" : "=l"(a) : "l"(x), "l"(w), "l"(a));
}

// ---------------------------------------------------------------------------
// Kernel 1: mask-dtype detect + alive flag + JAX partitionable threefry
// gumbel ranking (bits = out0 ^ out1).
// ---------------------------------------------------------------------------
__device__ __forceinline__ unsigned int rotl32(unsigned int x, int r) {
    return (x << r) | (x >> (32 - r));
}

__global__ void __launch_bounds__(JJ) k_select(const void* mask) {
    const int b = blockIdx.x;
    const int j = threadIdx.x;   // 256 threads

    __shared__ unsigned int red[2];
    __shared__ int s_fmt;
    if (j == 0) { red[0] = 1u; red[1] = 1u; }
    __syncthreads();
    {
        unsigned int v = ((const unsigned int*)mask)[j];
        if (v > 1u) atomicAnd(&red[0], 0u);
        if (!(v == 0u || v == 0x3F800000u)) atomicAnd(&red[1], 0u);
    }
    __syncthreads();
    if (j == 0) {
        int f = red[0] ? 1 : (red[1] ? 2 : 0);
        s_fmt = f;
        if (b == 0) g_fmt = f;
    }
    __syncthreads();
    const int fmt = s_fmt;

    if (j < WD) g_img_sum[b][j] = 0.0f;
    if (j == 0) g_img_cnt[b] = 0.0f;

    const int base = (b * JJ + j) * KK;
    bool alive = false;
    for (int k = 0; k < KK; k++) {
        if (mask_at(mask, fmt, base + k)) { alive = true; break; }
    }

    const unsigned int n = (unsigned int)(b * JJ + j);
    unsigned int x0 = 0u;
    unsigned int x1 = n;
    const unsigned int ks0 = 0u;
    const unsigned int ks1 = 42u;
    const unsigned int ks2 = 0x1BD11BDAu ^ 42u;
    x0 += ks0; x1 += ks1;
#define TF_ROUND(r) { x0 += x1; x1 = rotl32(x1, (r)); x1 ^= x0; }
    TF_ROUND(13) TF_ROUND(15) TF_ROUND(26) TF_ROUND(6)
    x0 += ks1; x1 += ks2 + 1u;
    TF_ROUND(17) TF_ROUND(29) TF_ROUND(16) TF_ROUND(24)
    x0 += ks2; x1 += ks0 + 2u;
    TF_ROUND(13) TF_ROUND(15) TF_ROUND(26) TF_ROUND(6)
    x0 += ks0; x1 += ks1 + 3u;
    TF_ROUND(17) TF_ROUND(29) TF_ROUND(16) TF_ROUND(24)
    x0 += ks1; x1 += ks2 + 4u;
    TF_ROUND(13) TF_ROUND(15) TF_ROUND(26) TF_ROUND(6)
    x0 += ks2; x1 += ks0 + 5u;
#undef TF_ROUND
    const unsigned int bits = x0 ^ x1;

    const unsigned int keyv = alive ? ((bits >> 9) | 0x80000000u) : 0u;

    __shared__ unsigned int sc[JJ];
    __shared__ int cnt;
    sc[j] = keyv;
    if (j == 0) cnt = 0;
    __syncthreads();

    int rank = 0;
    for (int t = 0; t < JJ; t++) {
        unsigned int s = sc[t];
        if (s > keyv || (s == keyv && t < j)) rank++;
    }
    if (rank < SS) {
        int slot = atomicAdd(&cnt, 1);
        g_sel[b][slot] = j;
    }
}

// ---------------------------------------------------------------------------
// Kernel 2: image branch over sampled rows (small: 512 rows x 384 pts).
// ---------------------------------------------------------------------------
__global__ void __launch_bounds__(128) k_image(
    const float* __restrict__ Imodel, const float* __restrict__ Iobs,
    const float* __restrict__ metadata, const void* __restrict__ mask,
    const float* __restrict__ W_img_in, const float* __restrict__ b_img_in,
    const float* __restrict__ W_img, const float* __restrict__ b_img)
{
    __shared__ __align__(16) float WT0[WD][CIN];
    __shared__ __align__(16) float WT[DEPTH][WD][WD];
    __shared__ float bs0[WD];
    __shared__ float bsd[DEPTH][WD];

    const int tid = threadIdx.x;
    for (int t = tid; t < CIN * WD; t += 128) { int i = t / WD, c = t % WD; WT0[c][i] = W_img_in[t]; }
    for (int t = tid; t < DEPTH * WD * WD; t += 128) {
        int d = t / (WD * WD); int r = t % (WD * WD); int i = r / WD, c = r % WD;
        WT[d][c][i] = W_img[t];
    }
    for (int t = tid; t < WD; t += 128) bs0[t] = b_img_in[t];
    for (int t = tid; t < DEPTH * WD; t += 128) bsd[t / WD][t % WD] = b_img[t];
    __syncthreads();

    const int blk = blockIdx.x;
    const int chunk = blk % 3;
    const int bs = blk / 3;
    const int b = bs / SS;
    const int s = bs % SS;
    const int j = g_sel[b][s];
    const int fmt = g_fmt;

    const int k = chunk * 128 + tid;
    const int p = (b * JJ + j) * KK + k;

    float x[CIN];
    x[0] = Imodel[p];
    x[1] = Iobs[p];
    const float* mdp = metadata + (size_t)p * CMETA;
#pragma unroll
    for (int i = 0; i < CMETA; i++) x[2 + i] = mdp[i];

    float h[WD], h2[WD];
#pragma unroll
    for (int c = 0; c < WD; c++) {
        float a = bs0[c];
#pragma unroll
        for (int i = 0; i < CIN; i++) a = fmaf(x[i], WT0[c][i], a);
        h[c] = a;
    }
#pragma unroll 1
    for (int d = 0; d < DEPTH; d++) {
#pragma unroll
        for (int c = 0; c < WD; c++) {
            float a = bsd[d][c];
#pragma unroll
            for (int i = 0; i < WD; i++) a = fmaf(h[i], WT[d][c][i], a);
            h2[c] = fmaxf(a, 0.0f);
        }
#pragma unroll
        for (int c = 0; c < WD; c++) h[c] = h2[c];
    }

    const float m = mask_at(mask, fmt, p) ? 1.0f : 0.0f;

#pragma unroll
    for (int c = 0; c < WD; c++) {
        float v = m * h[c];
#pragma unroll
        for (int o = 16; o > 0; o >>= 1) v += __shfl_xor_sync(0xFFFFFFFFu, v, o);
        if ((tid & 31) == 0) atomicAdd(&g_img_sum[b][c], v);
    }
    {
        float v = m;
#pragma unroll
        for (int o = 16; o > 0; o >>= 1) v += __shfl_xor_sync(0xFFFFFFFFu, v, o);
        if ((tid & 31) == 0) atomicAdd(&g_img_cnt[b], v);
    }
}

// ---------------------------------------------------------------------------
// Kernel 3: main branch with PACKED f32x2 FMA. Accumulator packs the
// (even-i, odd-i) partial sums; weight pairs come straight out of LDS.128
// halves (no duplication). 2 points/thread -> 4 FFMA2 per LDS.128.
// ---------------------------------------------------------------------------
__global__ void __launch_bounds__(TPB, 1) k_main(
    const float* __restrict__ metadata, const void* __restrict__ mask,
    const float* __restrict__ W_lin_in, const float* __restrict__ b_lin_in,
    const float* __restrict__ W_mlp, const float* __restrict__ b_mlp,
    const float* __restrict__ W_out, const float* __restrict__ b_out,
    float* __restrict__ out)
{
    __shared__ __align__(16) float W0s[WD * 8];            // [c][i], i padded 6->8
    __shared__ __align__(16) float Ws[DEPTH * WD * WD];    // [d][c][i] transposed
    __shared__ float beff[WD];                             // b_lin + image_rep[b]
    __shared__ float bsd[DEPTH][WD];
    __shared__ __align__(16) float wouts[WD];
    __shared__ float bout_s;

    const int tid = threadIdx.x;
    const int p0 = blockIdx.x * PTSBLK;
    const int b = p0 / JK;

    for (int t = tid; t < WD * 8; t += TPB) {
        int c = t >> 3, i = t & 7;
        W0s[t] = (i < CMETA) ? W_lin_in[i * WD + c] : 0.0f;
    }
    for (int t = tid; t < DEPTH * WD * WD; t += TPB) {
        int d = t / (WD * WD); int r = t % (WD * WD); int i = r / WD, c = r % WD;
        Ws[(d * WD + c) * WD + i] = W_mlp[t];
    }
    if (tid < WD) {
        beff[tid] = b_lin_in[tid] + g_img_sum[b][tid] / g_img_cnt[b];
        wouts[tid] = W_out[tid];
    }
    for (int t = tid; t < DEPTH * WD; t += TPB) bsd[t / WD][t % WD] = b_mlp[t];
    if (tid == 0) bout_s = b_out[0];
    __syncthreads();

    const int fmt = g_fmt;
    const int p = p0 + tid;
    const int q = p + TPB;

    // inputs: pack (x_{2i}, x_{2i+1}) pairs, padded 6->8
    unsigned long long xA[4], xB[4];
    {
        const float* m0 = metadata + (size_t)p * CMETA;
        const float* m1 = metadata + (size_t)q * CMETA;
        xA[0] = pack2(m0[0], m0[1]); xA[1] = pack2(m0[2], m0[3]);
        xA[2] = pack2(m0[4], m0[5]); xA[3] = 0ULL;
        xB[0] = pack2(m1[0], m1[1]); xB[1] = pack2(m1[2], m1[3]);
        xB[2] = pack2(m1[4], m1[5]); xB[3] = 0ULL;
    }

    unsigned long long hA[16], hB[16];

    // ---- input layer (no relu); beff = b_lin + image_rep folded ----
#pragma unroll
    for (int c = 0; c < WD; c += 2) {
        float rA[2], rB[2];
#pragma unroll
        for (int cc = 0; cc < 2; cc++) {
            const ulonglong2* wr = (const ulonglong2*)&W0s[(c + cc) * 8];
            unsigned long long aA = 0ULL, aB = 0ULL;
#pragma unroll
            for (int i4 = 0; i4 < 2; i4++) {
                ulonglong2 w = wr[i4];
                fma2(aA, xA[i4 * 2 + 0], w.x); fma2(aA, xA[i4 * 2 + 1], w.y);
                fma2(aB, xB[i4 * 2 + 0], w.x); fma2(aB, xB[i4 * 2 + 1], w.y);
            }
            float lo, hi;
            unpack2(aA, lo, hi); rA[cc] = beff[c + cc] + lo + hi;
            unpack2(aB, lo, hi); rB[cc] = beff[c + cc] + lo + hi;
        }
        hA[c >> 1] = pack2(rA[0], rA[1]);
        hB[c >> 1] = pack2(rB[0], rB[1]);
    }

    // ---- hidden layers (relu) ----
#pragma unroll 1
    for (int d = 0; d < DEPTH; d++) {
        const float* wl = &Ws[d * WD * WD];
        const float* bl = bsd[d];
        unsigned long long nA[16], nB[16];
#pragma unroll
        for (int c = 0; c < WD; c += 2) {
            float rA[2], rB[2];
#pragma unroll
            for (int cc = 0; cc < 2; cc++) {
                const ulonglong2* wr = (const ulonglong2*)&wl[(c + cc) * WD];
                unsigned long long aA = 0ULL, aB = 0ULL;
#pragma unroll
                for (int i4 = 0; i4 < 8; i4++) {
                    ulonglong2 w = wr[i4];
                    fma2(aA, hA[i4 * 2 + 0], w.x); fma2(aA, hA[i4 * 2 + 1], w.y);
                    fma2(aB, hB[i4 * 2 + 0], w.x); fma2(aB, hB[i4 * 2 + 1], w.y);
                }
                float lo, hi;
                unpack2(aA, lo, hi); rA[cc] = fmaxf(bl[c + cc] + lo + hi, 0.0f);
                unpack2(aB, lo, hi); rB[cc] = fmaxf(bl[c + cc] + lo + hi, 0.0f);
            }
            nA[c >> 1] = pack2(rA[0], rA[1]);
            nB[c >> 1] = pack2(rB[0], rB[1]);
        }
#pragma unroll
        for (int t = 0; t < 16; t++) { hA[t] = nA[t]; hB[t] = nB[t]; }
    }

    // ---- output layer ----
    unsigned long long oA = 0ULL, oB = 0ULL;
    const ulonglong2* wr = (const ulonglong2*)wouts;
#pragma unroll
    for (int i4 = 0; i4 < 8; i4++) {
        ulonglong2 w = wr[i4];
        fma2(oA, hA[i4 * 2 + 0], w.x); fma2(oA, hA[i4 * 2 + 1], w.y);
        fma2(oB, hB[i4 * 2 + 0], w.x); fma2(oB, hB[i4 * 2 + 1], w.y);
    }
    float lo, hi;
    unpack2(oA, lo, hi); float r0 = bout_s + lo + hi;
    unpack2(oB, lo, hi); float r1 = bout_s + lo + hi;

    out[p] = mask_at(mask, fmt, p) ? r0 : 0.0f;
    out[q] = mask_at(mask, fmt, q) ? r1 : 0.0f;
}

// ---------------------------------------------------------------------------
// Launch: select(+detect) -> image -> main (default stream, graph-capturable)
// ---------------------------------------------------------------------------
extern "C" void kernel_launch(void* const* d_in, const int* in_sizes, int n_in,
                              void* d_out, int out_size)
{
    const float* Imodel   = (const float*)d_in[0];
    const float* Iobs     = (const float*)d_in[1];
    const float* metadata = (const float*)d_in[2];
    const void*  mask     = d_in[3];
    // d_in[4] = sample_size (always 32)
    const float* W_img_in = (const float*)d_in[5];
    const float* b_img_in = (const float*)d_in[6];
    const float* W_img    = (const float*)d_in[7];
    const float* b_img    = (const float*)d_in[8];
    const float* W_lin_in = (const float*)d_in[9];
    const float* b_lin_in = (const float*)d_in[10];
    const float* W_mlp    = (const float*)d_in[11];
    const float* b_mlp    = (const float*)d_in[12];
    const float* W_out    = (const float*)d_in[13];
    const float* b_out    = (const float*)d_in[14];
    float* out = (float*)d_out;

    k_select<<<BB, JJ>>>(mask);
    k_image<<<BB * SS * 3, 128>>>(Imodel, Iobs, metadata, mask,
                                  W_img_in, b_img_in, W_img, b_img);
    k_main<<<NPTS / PTSBLK, TPB>>>(metadata, mask, W_lin_in, b_lin_in,
                                   W_mlp, b_mlp, W_out, b_out, out);
}

// round 7
// speedup vs baseline: 1.2532x; 1.2532x over previous
#include <cuda_runtime.h>
#include <math.h>

// Problem constants
#define BB     16
#define JJ     256
#define KK     384
#define CMETA  6
#define CIN    8      // C_MODEL(1) + C_OBS(1) + C_META(6)
#define WD     32
#define DEPTH  3
#define SS     32     // sample_size
#define JK     (JJ*KK)        // 98304
#define NPTS   (BB*JK)        // 1572864
#define TPB    256
#define PPT    2              // points per thread in k_main
#define PTSBLK (TPB*PPT)      // 512 slots per block

// Scratch (device globals; no allocation allowed)
__device__ int   g_fmt;                 // 0=uint8, 1=int32, 2=float32
__device__ int   g_sel[BB][SS];         // selected j indices per batch
__device__ float g_img_sum[BB][WD];     // masked sum of image-branch hidden
__device__ float g_img_cnt[BB];         // masked count
__device__ int   g_nact;                // number of active (masked-in) points
__device__ int   g_idx[NPTS];           // compacted active point indices

__device__ __forceinline__ bool mask_at(const void* m, int fmt, int i) {
    if (fmt == 0) return ((const unsigned char*)m)[i] != 0;
    if (fmt == 1) return ((const int*)m)[i] != 0;
    return ((const float*)m)[i] != 0.0f;
}

// ---------------------------------------------------------------------------
// Kernel 1: mask-dtype detect + alive flag + JAX partitionable threefry
// gumbel ranking (bits = out0 ^ out1). Also resets replay state.
// ---------------------------------------------------------------------------
__device__ __forceinline__ unsigned int rotl32(unsigned int x, int r) {
    return (x << r) | (x >> (32 - r));
}

__global__ void __launch_bounds__(JJ) k_select(const void* mask) {
    const int b = blockIdx.x;
    const int j = threadIdx.x;   // 256 threads

    __shared__ unsigned int red[2];
    __shared__ int s_fmt;
    if (j == 0) { red[0] = 1u; red[1] = 1u; }
    __syncthreads();
    {
        unsigned int v = ((const unsigned int*)mask)[j];
        if (v > 1u) atomicAnd(&red[0], 0u);
        if (!(v == 0u || v == 0x3F800000u)) atomicAnd(&red[1], 0u);
    }
    __syncthreads();
    if (j == 0) {
        int f = red[0] ? 1 : (red[1] ? 2 : 0);
        s_fmt = f;
        if (b == 0) { g_fmt = f; g_nact = 0; }   // reset for this replay
    }
    __syncthreads();
    const int fmt = s_fmt;

    if (j < WD) g_img_sum[b][j] = 0.0f;
    if (j == 0) g_img_cnt[b] = 0.0f;

    const int base = (b * JJ + j) * KK;
    bool alive = false;
    for (int k = 0; k < KK; k++) {
        if (mask_at(mask, fmt, base + k)) { alive = true; break; }
    }

    const unsigned int n = (unsigned int)(b * JJ + j);
    unsigned int x0 = 0u;
    unsigned int x1 = n;
    const unsigned int ks0 = 0u;
    const unsigned int ks1 = 42u;
    const unsigned int ks2 = 0x1BD11BDAu ^ 42u;
    x0 += ks0; x1 += ks1;
#define TF_ROUND(r) { x0 += x1; x1 = rotl32(x1, (r)); x1 ^= x0; }
    TF_ROUND(13) TF_ROUND(15) TF_ROUND(26) TF_ROUND(6)
    x0 += ks1; x1 += ks2 + 1u;
    TF_ROUND(17) TF_ROUND(29) TF_ROUND(16) TF_ROUND(24)
    x0 += ks2; x1 += ks0 + 2u;
    TF_ROUND(13) TF_ROUND(15) TF_ROUND(26) TF_ROUND(6)
    x0 += ks0; x1 += ks1 + 3u;
    TF_ROUND(17) TF_ROUND(29) TF_ROUND(16) TF_ROUND(24)
    x0 += ks1; x1 += ks2 + 4u;
    TF_ROUND(13) TF_ROUND(15) TF_ROUND(26) TF_ROUND(6)
    x0 += ks2; x1 += ks0 + 5u;
#undef TF_ROUND
    const unsigned int bits = x0 ^ x1;

    const unsigned int keyv = alive ? ((bits >> 9) | 0x80000000u) : 0u;

    __shared__ unsigned int sc[JJ];
    __shared__ int cnt;
    sc[j] = keyv;
    if (j == 0) cnt = 0;
    __syncthreads();

    int rank = 0;
    for (int t = 0; t < JJ; t++) {
        unsigned int s = sc[t];
        if (s > keyv || (s == keyv && t < j)) rank++;
    }
    if (rank < SS) {
        int slot = atomicAdd(&cnt, 1);
        g_sel[b][slot] = j;
    }
}

// ---------------------------------------------------------------------------
// Kernel 1b: stream-compact active point indices; zero inactive outputs.
// ---------------------------------------------------------------------------
#define CB   256
#define CPT  4
__global__ void __launch_bounds__(CB) k_compact(const void* __restrict__ mask,
                                                float* __restrict__ out)
{
    const int fmt = g_fmt;
    const int tid = threadIdx.x;
    const int lane = tid & 31;
    const unsigned int lt = (1u << lane) - 1u;
    const int base = blockIdx.x * CB * CPT;

#pragma unroll
    for (int r = 0; r < CPT; r++) {
        const int p = base + r * CB + tid;        // coalesced
        const bool act = mask_at(mask, fmt, p);
        const unsigned int bal = __ballot_sync(0xFFFFFFFFu, act);
        int pos = 0;
        if (lane == 0) pos = atomicAdd(&g_nact, __popc(bal));
        pos = __shfl_sync(0xFFFFFFFFu, pos, 0);
        if (act) g_idx[pos + __popc(bal & lt)] = p;
        else     out[p] = 0.0f;
    }
}

// ---------------------------------------------------------------------------
// Kernel 2: image branch over sampled rows (small: 512 rows x 384 pts).
// ---------------------------------------------------------------------------
__global__ void __launch_bounds__(128) k_image(
    const float* __restrict__ Imodel, const float* __restrict__ Iobs,
    const float* __restrict__ metadata, const void* __restrict__ mask,
    const float* __restrict__ W_img_in, const float* __restrict__ b_img_in,
    const float* __restrict__ W_img, const float* __restrict__ b_img)
{
    __shared__ __align__(16) float WT0[WD][CIN];
    __shared__ __align__(16) float WT[DEPTH][WD][WD];
    __shared__ float bs0[WD];
    __shared__ float bsd[DEPTH][WD];

    const int tid = threadIdx.x;
    for (int t = tid; t < CIN * WD; t += 128) { int i = t / WD, c = t % WD; WT0[c][i] = W_img_in[t]; }
    for (int t = tid; t < DEPTH * WD * WD; t += 128) {
        int d = t / (WD * WD); int r = t % (WD * WD); int i = r / WD, c = r % WD;
        WT[d][c][i] = W_img[t];
    }
    for (int t = tid; t < WD; t += 128) bs0[t] = b_img_in[t];
    for (int t = tid; t < DEPTH * WD; t += 128) bsd[t / WD][t % WD] = b_img[t];
    __syncthreads();

    const int blk = blockIdx.x;
    const int chunk = blk % 3;
    const int bs = blk / 3;
    const int b = bs / SS;
    const int s = bs % SS;
    const int j = g_sel[b][s];
    const int fmt = g_fmt;

    const int k = chunk * 128 + tid;
    const int p = (b * JJ + j) * KK + k;

    float x[CIN];
    x[0] = Imodel[p];
    x[1] = Iobs[p];
    const float* mdp = metadata + (size_t)p * CMETA;
#pragma unroll
    for (int i = 0; i < CMETA; i++) x[2 + i] = mdp[i];

    float h[WD], h2[WD];
#pragma unroll
    for (int c = 0; c < WD; c++) {
        float a = bs0[c];
#pragma unroll
        for (int i = 0; i < CIN; i++) a = fmaf(x[i], WT0[c][i], a);
        h[c] = a;
    }
#pragma unroll 1
    for (int d = 0; d < DEPTH; d++) {
#pragma unroll
        for (int c = 0; c < WD; c++) {
            float a = bsd[d][c];
#pragma unroll
            for (int i = 0; i < WD; i++) a = fmaf(h[i], WT[d][c][i], a);
            h2[c] = fmaxf(a, 0.0f);
        }
#pragma unroll
        for (int c = 0; c < WD; c++) h[c] = h2[c];
    }

    const float m = mask_at(mask, fmt, p) ? 1.0f : 0.0f;

#pragma unroll
    for (int c = 0; c < WD; c++) {
        float v = m * h[c];
#pragma unroll
        for (int o = 16; o > 0; o >>= 1) v += __shfl_xor_sync(0xFFFFFFFFu, v, o);
        if ((tid & 31) == 0) atomicAdd(&g_img_sum[b][c], v);
    }
    {
        float v = m;
#pragma unroll
        for (int o = 16; o > 0; o >>= 1) v += __shfl_xor_sync(0xFFFFFFFFu, v, o);
        if ((tid & 31) == 0) atomicAdd(&g_img_cnt[b], v);
    }
}

// ---------------------------------------------------------------------------
// Kernel 3: main branch over COMPACTED active points only (~50% of NPTS).
// P=2 points/thread; float4 weight reads (LDS.128), 8 FMAs per LDS.
// ---------------------------------------------------------------------------
__global__ void __launch_bounds__(TPB, 1) k_main(
    const float* __restrict__ metadata,
    const float* __restrict__ W_lin_in, const float* __restrict__ b_lin_in,
    const float* __restrict__ W_mlp, const float* __restrict__ b_mlp,
    const float* __restrict__ W_out, const float* __restrict__ b_out,
    float* __restrict__ out)
{
    __shared__ __align__(16) float W0s[WD * 8];            // [c][i], i padded 6->8
    __shared__ __align__(16) float Ws[DEPTH * WD * WD];    // [d][c][i] transposed
    __shared__ float beffs[BB][WD];                        // per-batch folded bias
    __shared__ float bsd[DEPTH][WD];
    __shared__ __align__(16) float wouts[WD];
    __shared__ float bout_s;

    const int tid = threadIdx.x;

    for (int t = tid; t < WD * 8; t += TPB) {
        int c = t >> 3, i = t & 7;
        W0s[t] = (i < CMETA) ? W_lin_in[i * WD + c] : 0.0f;
    }
    for (int t = tid; t < DEPTH * WD * WD; t += TPB) {
        int d = t / (WD * WD); int r = t % (WD * WD); int i = r / WD, c = r % WD;
        Ws[(d * WD + c) * WD + i] = W_mlp[t];
    }
    for (int t = tid; t < BB * WD; t += TPB) {
        int bb = t / WD, c = t % WD;
        beffs[bb][c] = b_lin_in[c] + g_img_sum[bb][c] / g_img_cnt[bb];
    }
    if (tid < WD) wouts[tid] = W_out[tid];
    for (int t = tid; t < DEPTH * WD; t += TPB) bsd[t / WD][t % WD] = b_mlp[t];
    if (tid == 0) bout_s = b_out[0];
    __syncthreads();

    const int n_act = g_nact;
    const int slotA = blockIdx.x * PTSBLK + tid;
    if (slotA >= n_act) return;                    // slotB > slotA, also invalid
    const int slotB = slotA + TPB;
    const bool validB = slotB < n_act;

    const int pA = g_idx[slotA];
    const int pB = validB ? g_idx[slotB] : pA;
    const int bA = pA / JK;
    const int bB = pB / JK;

    // inputs, padded to 8
    float x0[8], x1[8];
    {
        const float* m0 = metadata + (size_t)pA * CMETA;
        const float* m1 = metadata + (size_t)pB * CMETA;
#pragma unroll
        for (int i = 0; i < CMETA; i++) { x0[i] = m0[i]; x1[i] = m1[i]; }
        x0[6] = x0[7] = 0.0f; x1[6] = x1[7] = 0.0f;
    }

    float h0[WD], h1[WD], o0[WD], o1[WD];

    // input layer (per-batch folded bias)
#pragma unroll
    for (int c = 0; c < WD; c++) {
        float a0 = beffs[bA][c], a1 = beffs[bB][c];
        const float4* wr = (const float4*)&W0s[c * 8];
#pragma unroll
        for (int i4 = 0; i4 < 2; i4++) {
            float4 w = wr[i4];
            a0 = fmaf(x0[i4 * 4 + 0], w.x, a0);
            a0 = fmaf(x0[i4 * 4 + 1], w.y, a0);
            a0 = fmaf(x0[i4 * 4 + 2], w.z, a0);
            a0 = fmaf(x0[i4 * 4 + 3], w.w, a0);
            a1 = fmaf(x1[i4 * 4 + 0], w.x, a1);
            a1 = fmaf(x1[i4 * 4 + 1], w.y, a1);
            a1 = fmaf(x1[i4 * 4 + 2], w.z, a1);
            a1 = fmaf(x1[i4 * 4 + 3], w.w, a1);
        }
        h0[c] = a0; h1[c] = a1;
    }

    // hidden layers
#pragma unroll 1
    for (int d = 0; d < DEPTH; d++) {
        const float4* wl = (const float4*)&Ws[d * WD * WD];
#pragma unroll
        for (int c = 0; c < WD; c++) {
            float a0 = bsd[d][c], a1 = a0;
#pragma unroll
            for (int i4 = 0; i4 < 8; i4++) {
                float4 w = wl[c * 8 + i4];
                a0 = fmaf(h0[i4 * 4 + 0], w.x, a0);
                a0 = fmaf(h0[i4 * 4 + 1], w.y, a0);
                a0 = fmaf(h0[i4 * 4 + 2], w.z, a0);
                a0 = fmaf(h0[i4 * 4 + 3], w.w, a0);
                a1 = fmaf(h1[i4 * 4 + 0], w.x, a1);
                a1 = fmaf(h1[i4 * 4 + 1], w.y, a1);
                a1 = fmaf(h1[i4 * 4 + 2], w.z, a1);
                a1 = fmaf(h1[i4 * 4 + 3], w.w, a1);
            }
            o0[c] = fmaxf(a0, 0.0f);
            o1[c] = fmaxf(a1, 0.0f);
        }
#pragma unroll
        for (int c = 0; c < WD; c++) { h0[c] = o0[c]; h1[c] = o1[c]; }
    }

    // output layer
    float r0 = bout_s, r1 = bout_s;
    const float4* wo = (const float4*)wouts;
#pragma unroll
    for (int i4 = 0; i4 < 8; i4++) {
        float4 w = wo[i4];
        r0 = fmaf(h0[i4 * 4 + 0], w.x, r0);
        r0 = fmaf(h0[i4 * 4 + 1], w.y, r0);
        r0 = fmaf(h0[i4 * 4 + 2], w.z, r0);
        r0 = fmaf(h0[i4 * 4 + 3], w.w, r0);
        r1 = fmaf(h1[i4 * 4 + 0], w.x, r1);
        r1 = fmaf(h1[i4 * 4 + 1], w.y, r1);
        r1 = fmaf(h1[i4 * 4 + 2], w.z, r1);
        r1 = fmaf(h1[i4 * 4 + 3], w.w, r1);
    }

    out[pA] = r0;
    if (validB) out[pB] = r1;
}

// ---------------------------------------------------------------------------
// Launch: select(+detect) -> compact -> image -> main
// ---------------------------------------------------------------------------
extern "C" void kernel_launch(void* const* d_in, const int* in_sizes, int n_in,
                              void* d_out, int out_size)
{
    const float* Imodel   = (const float*)d_in[0];
    const float* Iobs     = (const float*)d_in[1];
    const float* metadata = (const float*)d_in[2];
    const void*  mask     = d_in[3];
    // d_in[4] = sample_size (always 32)
    const float* W_img_in = (const float*)d_in[5];
    const float* b_img_in = (const float*)d_in[6];
    const float* W_img    = (const float*)d_in[7];
    const float* b_img    = (const float*)d_in[8];
    const float* W_lin_in = (const float*)d_in[9];
    const float* b_lin_in = (const float*)d_in[10];
    const float* W_mlp    = (const float*)d_in[11];
    const float* b_mlp    = (const float*)d_in[12];
    const float* W_out    = (const float*)d_in[13];
    const float* b_out    = (const float*)d_in[14];
    float* out = (float*)d_out;

    k_select<<<BB, JJ>>>(mask);
    k_compact<<<NPTS / (CB * CPT), CB>>>(mask, out);
    k_image<<<BB * SS * 3, 128>>>(Imodel, Iobs, metadata, mask,
                                  W_img_in, b_img_in, W_img, b_img);
    k_main<<<NPTS / PTSBLK, TPB>>>(metadata, W_lin_in, b_lin_in,
                                   W_mlp, b_mlp, W_out, b_out, out);
}

// round 8
// speedup vs baseline: 1.4796x; 1.1806x over previous
#include <cuda_runtime.h>
#include <math.h>

// Problem constants
#define BB     16
#define JJ     256
#define KK     384
#define CMETA  6
#define CIN    8      // C_MODEL(1) + C_OBS(1) + C_META(6)
#define WD     32
#define DEPTH  3
#define SS     32     // sample_size
#define JK     (JJ*KK)        // 98304
#define NPTS   (BB*JK)        // 1572864
#define TPB    256
#define PPT    2
#define PTSBLK (TPB*PPT)      // 512 slots per k_main block
#define NMAINB (NPTS/PTSBLK)  // 3072

// compact config (blocks 16.. in merged kernel)
#define CB   256
#define CPT  4
#define NCOMPB (NPTS/(CB*CPT))   // 1536

// Scratch (device globals; zero-initialized once at module load)
__device__ int   g_fmt;
__device__ int   g_sel[BB][SS];
__device__ float g_img_sum[BB][WD];
__device__ float g_img_cnt[BB];
__device__ int   g_nact;        // active-point counter (reset by k_main's last block)
__device__ int   g_done;        // k_main block-completion counter
__device__ int   g_idx[NPTS];

__device__ __forceinline__ bool mask_at(const void* m, int fmt, int i) {
    if (fmt == 0) return ((const unsigned char*)m)[i] != 0;
    if (fmt == 1) return ((const int*)m)[i] != 0;
    return ((const float*)m)[i] != 0.0f;
}

__device__ __forceinline__ int detect_fmt_block(const void* mask) {
    // 256 threads: inspect first 256 words; block-wide AND
    unsigned int v = ((const unsigned int*)mask)[threadIdx.x];
    int all_int = __syncthreads_and(v <= 1u);
    int all_flt = __syncthreads_and(v == 0u || v == 0x3F800000u);
    return all_int ? 1 : (all_flt ? 2 : 0);
}

__device__ __forceinline__ unsigned int rotl32(unsigned int x, int r) {
    return (x << r) | (x >> (32 - r));
}

// ---------------------------------------------------------------------------
// Kernel 1 (merged): blocks [0,16) = gumbel top-32 selection per batch;
// blocks [16, 16+NCOMPB) = stream compaction of active points + zero inactive.
// Both roles self-detect the mask dtype; no cross-block dependency.
// g_nact starts at 0 (static init / reset by previous k_main).
// ---------------------------------------------------------------------------
__global__ void __launch_bounds__(256) k_sc(const void* __restrict__ mask,
                                            float* __restrict__ out)
{
    const int fmt = detect_fmt_block(mask);
    const int tid = threadIdx.x;

    if (blockIdx.x >= 16) {
        // ---------------- compaction role ----------------
        const int cb = blockIdx.x - 16;
        const int lane = tid & 31;
        const unsigned int lt = (1u << lane) - 1u;
        const int base = cb * CB * CPT;
#pragma unroll
        for (int r = 0; r < CPT; r++) {
            const int p = base + r * CB + tid;    // coalesced
            const bool act = mask_at(mask, fmt, p);
            const unsigned int bal = __ballot_sync(0xFFFFFFFFu, act);
            int pos = 0;
            if (lane == 0) pos = atomicAdd(&g_nact, __popc(bal));
            pos = __shfl_sync(0xFFFFFFFFu, pos, 0);
            if (act) g_idx[pos + __popc(bal & lt)] = p;
            else     out[p] = 0.0f;
        }
        return;
    }

    // ---------------- selection role ----------------
    const int b = blockIdx.x;
    const int j = tid;

    if (j == 0 && b == 0) g_fmt = fmt;
    if (j < WD) g_img_sum[b][j] = 0.0f;
    if (j == 0) g_img_cnt[b] = 0.0f;

    const int base = (b * JJ + j) * KK;
    bool alive = false;
    for (int k = 0; k < KK; k++) {
        if (mask_at(mask, fmt, base + k)) { alive = true; break; }
    }

    // JAX partitionable threefry2x32, key=(0,42), counter n; bits = out0^out1
    const unsigned int n = (unsigned int)(b * JJ + j);
    unsigned int x0 = 0u;
    unsigned int x1 = n;
    const unsigned int ks0 = 0u;
    const unsigned int ks1 = 42u;
    const unsigned int ks2 = 0x1BD11BDAu ^ 42u;
    x0 += ks0; x1 += ks1;
#define TF_ROUND(r) { x0 += x1; x1 = rotl32(x1, (r)); x1 ^= x0; }
    TF_ROUND(13) TF_ROUND(15) TF_ROUND(26) TF_ROUND(6)
    x0 += ks1; x1 += ks2 + 1u;
    TF_ROUND(17) TF_ROUND(29) TF_ROUND(16) TF_ROUND(24)
    x0 += ks2; x1 += ks0 + 2u;
    TF_ROUND(13) TF_ROUND(15) TF_ROUND(26) TF_ROUND(6)
    x0 += ks0; x1 += ks1 + 3u;
    TF_ROUND(17) TF_ROUND(29) TF_ROUND(16) TF_ROUND(24)
    x0 += ks1; x1 += ks2 + 4u;
    TF_ROUND(13) TF_ROUND(15) TF_ROUND(26) TF_ROUND(6)
    x0 += ks2; x1 += ks0 + 5u;
#undef TF_ROUND
    const unsigned int bits = x0 ^ x1;

    const unsigned int keyv = alive ? ((bits >> 9) | 0x80000000u) : 0u;

    __shared__ unsigned int sc[JJ];
    __shared__ int cnt;
    sc[j] = keyv;
    if (j == 0) cnt = 0;
    __syncthreads();

    int rank = 0;
    for (int t = 0; t < JJ; t++) {
        unsigned int s = sc[t];
        if (s > keyv || (s == keyv && t < j)) rank++;
    }
    if (rank < SS) {
        int slot = atomicAdd(&cnt, 1);
        g_sel[b][slot] = j;
    }
}

// ---------------------------------------------------------------------------
// Kernel 2: image branch, float4 weights + 2 pts/thread.
// grid = BB*SS (one block per sampled row), 192 threads, k = tid and tid+192.
// ---------------------------------------------------------------------------
#define ITB 192
__global__ void __launch_bounds__(ITB) k_image(
    const float* __restrict__ Imodel, const float* __restrict__ Iobs,
    const float* __restrict__ metadata, const void* __restrict__ mask,
    const float* __restrict__ W_img_in, const float* __restrict__ b_img_in,
    const float* __restrict__ W_img, const float* __restrict__ b_img)
{
    __shared__ __align__(16) float W0s[WD * CIN];          // [c][i], CIN=8
    __shared__ __align__(16) float Ws[DEPTH * WD * WD];    // [d][c][i]
    __shared__ float bs0[WD];
    __shared__ float bsd[DEPTH][WD];

    const int tid = threadIdx.x;
    for (int t = tid; t < CIN * WD; t += ITB) {
        int i = t / WD, c = t % WD;
        W0s[c * CIN + i] = W_img_in[t];
    }
    for (int t = tid; t < DEPTH * WD * WD; t += ITB) {
        int d = t / (WD * WD); int r = t % (WD * WD); int i = r / WD, c = r % WD;
        Ws[(d * WD + c) * WD + i] = W_img[t];
    }
    for (int t = tid; t < WD; t += ITB) bs0[t] = b_img_in[t];
    for (int t = tid; t < DEPTH * WD; t += ITB) bsd[t / WD][t % WD] = b_img[t];
    __syncthreads();

    const int b = blockIdx.x / SS;
    const int s = blockIdx.x % SS;
    const int j = g_sel[b][s];
    const int fmt = g_fmt;

    const int base = (b * JJ + j) * KK;
    const int pA = base + tid;            // k in [0,192)
    const int pB = base + tid + ITB;      // k in [192,384)

    float x0[CIN], x1[CIN];
    x0[0] = Imodel[pA]; x1[0] = Imodel[pB];
    x0[1] = Iobs[pA];   x1[1] = Iobs[pB];
    {
        const float* m0 = metadata + (size_t)pA * CMETA;
        const float* m1 = metadata + (size_t)pB * CMETA;
#pragma unroll
        for (int i = 0; i < CMETA; i++) { x0[2 + i] = m0[i]; x1[2 + i] = m1[i]; }
    }

    float h0[WD], h1[WD], o0[WD], o1[WD];

#pragma unroll
    for (int c = 0; c < WD; c++) {
        float a0 = bs0[c], a1 = a0;
        const float4* wr = (const float4*)&W0s[c * CIN];
#pragma unroll
        for (int i4 = 0; i4 < 2; i4++) {
            float4 w = wr[i4];
            a0 = fmaf(x0[i4 * 4 + 0], w.x, a0);
            a0 = fmaf(x0[i4 * 4 + 1], w.y, a0);
            a0 = fmaf(x0[i4 * 4 + 2], w.z, a0);
            a0 = fmaf(x0[i4 * 4 + 3], w.w, a0);
            a1 = fmaf(x1[i4 * 4 + 0], w.x, a1);
            a1 = fmaf(x1[i4 * 4 + 1], w.y, a1);
            a1 = fmaf(x1[i4 * 4 + 2], w.z, a1);
            a1 = fmaf(x1[i4 * 4 + 3], w.w, a1);
        }
        h0[c] = a0; h1[c] = a1;
    }

#pragma unroll 1
    for (int d = 0; d < DEPTH; d++) {
        const float4* wl = (const float4*)&Ws[d * WD * WD];
#pragma unroll
        for (int c = 0; c < WD; c++) {
            float a0 = bsd[d][c], a1 = a0;
#pragma unroll
            for (int i4 = 0; i4 < 8; i4++) {
                float4 w = wl[c * 8 + i4];
                a0 = fmaf(h0[i4 * 4 + 0], w.x, a0);
                a0 = fmaf(h0[i4 * 4 + 1], w.y, a0);
                a0 = fmaf(h0[i4 * 4 + 2], w.z, a0);
                a0 = fmaf(h0[i4 * 4 + 3], w.w, a0);
                a1 = fmaf(h1[i4 * 4 + 0], w.x, a1);
                a1 = fmaf(h1[i4 * 4 + 1], w.y, a1);
                a1 = fmaf(h1[i4 * 4 + 2], w.z, a1);
                a1 = fmaf(h1[i4 * 4 + 3], w.w, a1);
            }
            o0[c] = fmaxf(a0, 0.0f);
            o1[c] = fmaxf(a1, 0.0f);
        }
#pragma unroll
        for (int c = 0; c < WD; c++) { h0[c] = o0[c]; h1[c] = o1[c]; }
    }

    const float m0 = mask_at(mask, fmt, pA) ? 1.0f : 0.0f;
    const float m1 = mask_at(mask, fmt, pB) ? 1.0f : 0.0f;

#pragma unroll
    for (int c = 0; c < WD; c++) {
        float v = m0 * h0[c] + m1 * h1[c];
#pragma unroll
        for (int o = 16; o > 0; o >>= 1) v += __shfl_xor_sync(0xFFFFFFFFu, v, o);
        if ((tid & 31) == 0) atomicAdd(&g_img_sum[b][c], v);
    }
    {
        float v = m0 + m1;
#pragma unroll
        for (int o = 16; o > 0; o >>= 1) v += __shfl_xor_sync(0xFFFFFFFFu, v, o);
        if ((tid & 31) == 0) atomicAdd(&g_img_cnt[b], v);
    }
}

// ---------------------------------------------------------------------------
// Kernel 3: main branch over compacted active points. P=2, float4 weights.
// Last-finishing block resets g_nact/g_done for the next graph replay.
// ---------------------------------------------------------------------------
__global__ void __launch_bounds__(TPB, 1) k_main(
    const float* __restrict__ metadata,
    const float* __restrict__ W_lin_in, const float* __restrict__ b_lin_in,
    const float* __restrict__ W_mlp, const float* __restrict__ b_mlp,
    const float* __restrict__ W_out, const float* __restrict__ b_out,
    float* __restrict__ out)
{
    __shared__ __align__(16) float W0s[WD * 8];
    __shared__ __align__(16) float Ws[DEPTH * WD * WD];
    __shared__ float beffs[BB][WD];
    __shared__ float bsd[DEPTH][WD];
    __shared__ __align__(16) float wouts[WD];
    __shared__ float bout_s;

    const int tid = threadIdx.x;

    for (int t = tid; t < WD * 8; t += TPB) {
        int c = t >> 3, i = t & 7;
        W0s[t] = (i < CMETA) ? W_lin_in[i * WD + c] : 0.0f;
    }
    for (int t = tid; t < DEPTH * WD * WD; t += TPB) {
        int d = t / (WD * WD); int r = t % (WD * WD); int i = r / WD, c = r % WD;
        Ws[(d * WD + c) * WD + i] = W_mlp[t];
    }
    for (int t = tid; t < BB * WD; t += TPB) {
        int bb = t / WD, c = t % WD;
        beffs[bb][c] = b_lin_in[c] + g_img_sum[bb][c] / g_img_cnt[bb];
    }
    if (tid < WD) wouts[tid] = W_out[tid];
    for (int t = tid; t < DEPTH * WD; t += TPB) bsd[t / WD][t % WD] = b_mlp[t];
    if (tid == 0) bout_s = b_out[0];
    __syncthreads();

    const int n_act = g_nact;
    const int slotA = blockIdx.x * PTSBLK + tid;

    if (slotA < n_act) {
        const int slotB = slotA + TPB;
        const bool validB = slotB < n_act;

        const int pA = g_idx[slotA];
        const int pB = validB ? g_idx[slotB] : pA;
        const int bA = pA / JK;
        const int bB = pB / JK;

        float x0[8], x1[8];
        {
            const float* m0 = metadata + (size_t)pA * CMETA;
            const float* m1 = metadata + (size_t)pB * CMETA;
#pragma unroll
            for (int i = 0; i < CMETA; i++) { x0[i] = m0[i]; x1[i] = m1[i]; }
            x0[6] = x0[7] = 0.0f; x1[6] = x1[7] = 0.0f;
        }

        float h0[WD], h1[WD], o0[WD], o1[WD];

#pragma unroll
        for (int c = 0; c < WD; c++) {
            float a0 = beffs[bA][c], a1 = beffs[bB][c];
            const float4* wr = (const float4*)&W0s[c * 8];
#pragma unroll
            for (int i4 = 0; i4 < 2; i4++) {
                float4 w = wr[i4];
                a0 = fmaf(x0[i4 * 4 + 0], w.x, a0);
                a0 = fmaf(x0[i4 * 4 + 1], w.y, a0);
                a0 = fmaf(x0[i4 * 4 + 2], w.z, a0);
                a0 = fmaf(x0[i4 * 4 + 3], w.w, a0);
                a1 = fmaf(x1[i4 * 4 + 0], w.x, a1);
                a1 = fmaf(x1[i4 * 4 + 1], w.y, a1);
                a1 = fmaf(x1[i4 * 4 + 2], w.z, a1);
                a1 = fmaf(x1[i4 * 4 + 3], w.w, a1);
            }
            h0[c] = a0; h1[c] = a1;
        }

#pragma unroll 1
        for (int d = 0; d < DEPTH; d++) {
            const float4* wl = (const float4*)&Ws[d * WD * WD];
#pragma unroll
            for (int c = 0; c < WD; c++) {
                float a0 = bsd[d][c], a1 = a0;
#pragma unroll
                for (int i4 = 0; i4 < 8; i4++) {
                    float4 w = wl[c * 8 + i4];
                    a0 = fmaf(h0[i4 * 4 + 0], w.x, a0);
                    a0 = fmaf(h0[i4 * 4 + 1], w.y, a0);
                    a0 = fmaf(h0[i4 * 4 + 2], w.z, a0);
                    a0 = fmaf(h0[i4 * 4 + 3], w.w, a0);
                    a1 = fmaf(h1[i4 * 4 + 0], w.x, a1);
                    a1 = fmaf(h1[i4 * 4 + 1], w.y, a1);
                    a1 = fmaf(h1[i4 * 4 + 2], w.z, a1);
                    a1 = fmaf(h1[i4 * 4 + 3], w.w, a1);
                }
                o0[c] = fmaxf(a0, 0.0f);
                o1[c] = fmaxf(a1, 0.0f);
            }
#pragma unroll
            for (int c = 0; c < WD; c++) { h0[c] = o0[c]; h1[c] = o1[c]; }
        }

        float r0 = bout_s, r1 = bout_s;
        const float4* wo = (const float4*)wouts;
#pragma unroll
        for (int i4 = 0; i4 < 8; i4++) {
            float4 w = wo[i4];
            r0 = fmaf(h0[i4 * 4 + 0], w.x, r0);
            r0 = fmaf(h0[i4 * 4 + 1], w.y, r0);
            r0 = fmaf(h0[i4 * 4 + 2], w.z, r0);
            r0 = fmaf(h0[i4 * 4 + 3], w.w, r0);
            r1 = fmaf(h1[i4 * 4 + 0], w.x, r1);
            r1 = fmaf(h1[i4 * 4 + 1], w.y, r1);
            r1 = fmaf(h1[i4 * 4 + 2], w.z, r1);
            r1 = fmaf(h1[i4 * 4 + 3], w.w, r1);
        }

        out[pA] = r0;
        if (validB) out[pB] = r1;
    }

    // replay-state reset: last block out (after ALL blocks have read g_nact)
    __syncthreads();
    if (tid == 0) {
        int old = atomicAdd(&g_done, 1);
        if (old == (int)gridDim.x - 1) {
            g_nact = 0;
            __threadfence();
            g_done = 0;
        }
    }
}

// ---------------------------------------------------------------------------
// Launch: sc (select ∥ compact) -> image -> main
// ---------------------------------------------------------------------------
extern "C" void kernel_launch(void* const* d_in, const int* in_sizes, int n_in,
                              void* d_out, int out_size)
{
    const float* Imodel   = (const float*)d_in[0];
    const float* Iobs     = (const float*)d_in[1];
    const float* metadata = (const float*)d_in[2];
    const void*  mask     = d_in[3];
    // d_in[4] = sample_size (always 32)
    const float* W_img_in = (const float*)d_in[5];
    const float* b_img_in = (const float*)d_in[6];
    const float* W_img    = (const float*)d_in[7];
    const float* b_img    = (const float*)d_in[8];
    const float* W_lin_in = (const float*)d_in[9];
    const float* b_lin_in = (const float*)d_in[10];
    const float* W_mlp    = (const float*)d_in[11];
    const float* b_mlp    = (const float*)d_in[12];
    const float* W_out    = (const float*)d_in[13];
    const float* b_out    = (const float*)d_in[14];
    float* out = (float*)d_out;

    k_sc<<<16 + NCOMPB, 256>>>(mask, out);
    k_image<<<BB * SS, ITB>>>(Imodel, Iobs, metadata, mask,
                              W_img_in, b_img_in, W_img, b_img);
    k_main<<<NMAINB, TPB>>>(metadata, W_lin_in, b_lin_in,
                            W_mlp, b_mlp, W_out, b_out, out);
}

// round 9
// speedup vs baseline: 1.5308x; 1.0345x over previous
#include <cuda_runtime.h>
#include <math.h>

// Problem constants
#define BB     16
#define JJ     256
#define KK     384
#define CMETA  6
#define CIN    8      // C_MODEL(1) + C_OBS(1) + C_META(6)
#define WD     32
#define DEPTH  3
#define SS     32     // sample_size
#define JK     (JJ*KK)        // 98304
#define NPTS   (BB*JK)        // 1572864
#define TPB    128
#define PPT    2
#define PTSBLK (TPB*PPT)      // 256 slots per k_main block
#define NMAINB (NPTS/PTSBLK)  // 6144

// compact config (blocks 16.. in merged kernel)
#define CB   256
#define CPT  4
#define NCOMPB (NPTS/(CB*CPT))   // 1536

// Scratch (device globals; zero-initialized once at module load)
__device__ int   g_fmt;
__device__ int   g_sel[BB][SS];
__device__ float g_img_sum[BB][WD];
__device__ float g_img_cnt[BB];
__device__ int   g_nact;        // active-point counter (reset by k_main's last block)
__device__ int   g_done;        // k_main block-completion counter
__device__ int   g_idx[NPTS];

__device__ __forceinline__ bool mask_at(const void* m, int fmt, int i) {
    if (fmt == 0) return ((const unsigned char*)m)[i] != 0;
    if (fmt == 1) return ((const int*)m)[i] != 0;
    return ((const float*)m)[i] != 0.0f;
}

__device__ __forceinline__ int detect_fmt_block(const void* mask) {
    // 256 threads: inspect first 256 words; block-wide AND
    unsigned int v = ((const unsigned int*)mask)[threadIdx.x];
    int all_int = __syncthreads_and(v <= 1u);
    int all_flt = __syncthreads_and(v == 0u || v == 0x3F800000u);
    return all_int ? 1 : (all_flt ? 2 : 0);
}

__device__ __forceinline__ unsigned int rotl32(unsigned int x, int r) {
    return (x << r) | (x >> (32 - r));
}

// ---------------------------------------------------------------------------
// Kernel 1 (merged): blocks [0,16) = gumbel top-32 selection per batch;
// blocks [16, 16+NCOMPB) = stream compaction with BLOCK-AGGREGATED atomics
// (1 atomicAdd per block instead of per warp per iter).
// ---------------------------------------------------------------------------
__global__ void __launch_bounds__(256) k_sc(const void* __restrict__ mask,
                                            float* __restrict__ out)
{
    const int fmt = detect_fmt_block(mask);
    const int tid = threadIdx.x;

    if (blockIdx.x >= 16) {
        // ---------------- compaction role (block-aggregated) ----------------
        const int cb = blockIdx.x - 16;
        const int lane = tid & 31;
        const int wid = tid >> 5;                 // 8 warps
        const unsigned int lt = (1u << lane) - 1u;
        const int base = cb * CB * CPT;

        bool act[CPT];
        unsigned int bal[CPT];
        int wcnt = 0;
#pragma unroll
        for (int r = 0; r < CPT; r++) {
            const int p = base + r * CB + tid;    // coalesced
            act[r] = mask_at(mask, fmt, p);
            bal[r] = __ballot_sync(0xFFFFFFFFu, act[r]);
            wcnt += __popc(bal[r]);
            if (!act[r]) out[p] = 0.0f;
        }

        __shared__ int wsum[8];
        __shared__ int bbase;
        if (lane == 0) wsum[wid] = wcnt;
        __syncthreads();
        if (tid == 0) {
            int tot = 0;
#pragma unroll
            for (int w = 0; w < 8; w++) { int c = wsum[w]; wsum[w] = tot; tot += c; }
            bbase = atomicAdd(&g_nact, tot);
        }
        __syncthreads();

        int off = bbase + wsum[wid];
#pragma unroll
        for (int r = 0; r < CPT; r++) {
            if (act[r]) g_idx[off + __popc(bal[r] & lt)] = base + r * CB + tid;
            off += __popc(bal[r]);
        }
        return;
    }

    // ---------------- selection role ----------------
    const int b = blockIdx.x;
    const int j = tid;

    if (j == 0 && b == 0) g_fmt = fmt;
    if (j < WD) g_img_sum[b][j] = 0.0f;
    if (j == 0) g_img_cnt[b] = 0.0f;

    const int base = (b * JJ + j) * KK;
    bool alive = false;
    for (int k = 0; k < KK; k++) {
        if (mask_at(mask, fmt, base + k)) { alive = true; break; }
    }

    // JAX partitionable threefry2x32, key=(0,42), counter n; bits = out0^out1
    const unsigned int n = (unsigned int)(b * JJ + j);
    unsigned int x0 = 0u;
    unsigned int x1 = n;
    const unsigned int ks0 = 0u;
    const unsigned int ks1 = 42u;
    const unsigned int ks2 = 0x1BD11BDAu ^ 42u;
    x0 += ks0; x1 += ks1;
#define TF_ROUND(r) { x0 += x1; x1 = rotl32(x1, (r)); x1 ^= x0; }
    TF_ROUND(13) TF_ROUND(15) TF_ROUND(26) TF_ROUND(6)
    x0 += ks1; x1 += ks2 + 1u;
    TF_ROUND(17) TF_ROUND(29) TF_ROUND(16) TF_ROUND(24)
    x0 += ks2; x1 += ks0 + 2u;
    TF_ROUND(13) TF_ROUND(15) TF_ROUND(26) TF_ROUND(6)
    x0 += ks0; x1 += ks1 + 3u;
    TF_ROUND(17) TF_ROUND(29) TF_ROUND(16) TF_ROUND(24)
    x0 += ks1; x1 += ks2 + 4u;
    TF_ROUND(13) TF_ROUND(15) TF_ROUND(26) TF_ROUND(6)
    x0 += ks2; x1 += ks0 + 5u;
#undef TF_ROUND
    const unsigned int bits = x0 ^ x1;

    const unsigned int keyv = alive ? ((bits >> 9) | 0x80000000u) : 0u;

    __shared__ unsigned int sc[JJ];
    __shared__ int cnt;
    sc[j] = keyv;
    if (j == 0) cnt = 0;
    __syncthreads();

    int rank = 0;
    for (int t = 0; t < JJ; t++) {
        unsigned int s = sc[t];
        if (s > keyv || (s == keyv && t < j)) rank++;
    }
    if (rank < SS) {
        int slot = atomicAdd(&cnt, 1);
        g_sel[b][slot] = j;
    }
}

// ---------------------------------------------------------------------------
// Kernel 2: image branch, float4 weights + 2 pts/thread.
// ---------------------------------------------------------------------------
#define ITB 192
__global__ void __launch_bounds__(ITB) k_image(
    const float* __restrict__ Imodel, const float* __restrict__ Iobs,
    const float* __restrict__ metadata, const void* __restrict__ mask,
    const float* __restrict__ W_img_in, const float* __restrict__ b_img_in,
    const float* __restrict__ W_img, const float* __restrict__ b_img)
{
    __shared__ __align__(16) float W0s[WD * CIN];
    __shared__ __align__(16) float Ws[DEPTH * WD * WD];
    __shared__ float bs0[WD];
    __shared__ float bsd[DEPTH][WD];

    const int tid = threadIdx.x;
    for (int t = tid; t < CIN * WD; t += ITB) {
        int i = t / WD, c = t % WD;
        W0s[c * CIN + i] = W_img_in[t];
    }
    for (int t = tid; t < DEPTH * WD * WD; t += ITB) {
        int d = t / (WD * WD); int r = t % (WD * WD); int i = r / WD, c = r % WD;
        Ws[(d * WD + c) * WD + i] = W_img[t];
    }
    for (int t = tid; t < WD; t += ITB) bs0[t] = b_img_in[t];
    for (int t = tid; t < DEPTH * WD; t += ITB) bsd[t / WD][t % WD] = b_img[t];
    __syncthreads();

    const int b = blockIdx.x / SS;
    const int s = blockIdx.x % SS;
    const int j = g_sel[b][s];
    const int fmt = g_fmt;

    const int base = (b * JJ + j) * KK;
    const int pA = base + tid;
    const int pB = base + tid + ITB;

    float x0[CIN], x1[CIN];
    x0[0] = Imodel[pA]; x1[0] = Imodel[pB];
    x0[1] = Iobs[pA];   x1[1] = Iobs[pB];
    {
        const float* m0 = metadata + (size_t)pA * CMETA;
        const float* m1 = metadata + (size_t)pB * CMETA;
#pragma unroll
        for (int i = 0; i < CMETA; i++) { x0[2 + i] = m0[i]; x1[2 + i] = m1[i]; }
    }

    float h0[WD], h1[WD], o0[WD], o1[WD];

#pragma unroll
    for (int c = 0; c < WD; c++) {
        float a0 = bs0[c], a1 = a0;
        const float4* wr = (const float4*)&W0s[c * CIN];
#pragma unroll
        for (int i4 = 0; i4 < 2; i4++) {
            float4 w = wr[i4];
            a0 = fmaf(x0[i4 * 4 + 0], w.x, a0);
            a0 = fmaf(x0[i4 * 4 + 1], w.y, a0);
            a0 = fmaf(x0[i4 * 4 + 2], w.z, a0);
            a0 = fmaf(x0[i4 * 4 + 3], w.w, a0);
            a1 = fmaf(x1[i4 * 4 + 0], w.x, a1);
            a1 = fmaf(x1[i4 * 4 + 1], w.y, a1);
            a1 = fmaf(x1[i4 * 4 + 2], w.z, a1);
            a1 = fmaf(x1[i4 * 4 + 3], w.w, a1);
        }
        h0[c] = a0; h1[c] = a1;
    }

#pragma unroll 1
    for (int d = 0; d < DEPTH; d++) {
        const float4* wl = (const float4*)&Ws[d * WD * WD];
#pragma unroll
        for (int c = 0; c < WD; c++) {
            float a0 = bsd[d][c], a1 = a0;
#pragma unroll
            for (int i4 = 0; i4 < 8; i4++) {
                float4 w = wl[c * 8 + i4];
                a0 = fmaf(h0[i4 * 4 + 0], w.x, a0);
                a0 = fmaf(h0[i4 * 4 + 1], w.y, a0);
                a0 = fmaf(h0[i4 * 4 + 2], w.z, a0);
                a0 = fmaf(h0[i4 * 4 + 3], w.w, a0);
                a1 = fmaf(h1[i4 * 4 + 0], w.x, a1);
                a1 = fmaf(h1[i4 * 4 + 1], w.y, a1);
                a1 = fmaf(h1[i4 * 4 + 2], w.z, a1);
                a1 = fmaf(h1[i4 * 4 + 3], w.w, a1);
            }
            o0[c] = fmaxf(a0, 0.0f);
            o1[c] = fmaxf(a1, 0.0f);
        }
#pragma unroll
        for (int c = 0; c < WD; c++) { h0[c] = o0[c]; h1[c] = o1[c]; }
    }

    const float m0 = mask_at(mask, fmt, pA) ? 1.0f : 0.0f;
    const float m1 = mask_at(mask, fmt, pB) ? 1.0f : 0.0f;

#pragma unroll
    for (int c = 0; c < WD; c++) {
        float v = m0 * h0[c] + m1 * h1[c];
#pragma unroll
        for (int o = 16; o > 0; o >>= 1) v += __shfl_xor_sync(0xFFFFFFFFu, v, o);
        if ((tid & 31) == 0) atomicAdd(&g_img_sum[b][c], v);
    }
    {
        float v = m0 + m1;
#pragma unroll
        for (int o = 16; o > 0; o >>= 1) v += __shfl_xor_sync(0xFFFFFFFFu, v, o);
        if ((tid & 31) == 0) atomicAdd(&g_img_cnt[b], v);
    }
}

// ---------------------------------------------------------------------------
// Kernel 3: main branch over compacted active points. P=2, float4 weights.
// TPB=128 with min-3-blocks/SM for 12 warps/SM latency hiding.
// ---------------------------------------------------------------------------
__global__ void __launch_bounds__(TPB, 3) k_main(
    const float* __restrict__ metadata,
    const float* __restrict__ W_lin_in, const float* __restrict__ b_lin_in,
    const float* __restrict__ W_mlp, const float* __restrict__ b_mlp,
    const float* __restrict__ W_out, const float* __restrict__ b_out,
    float* __restrict__ out)
{
    __shared__ __align__(16) float W0s[WD * 8];
    __shared__ __align__(16) float Ws[DEPTH * WD * WD];
    __shared__ float beffs[BB][WD];
    __shared__ float bsd[DEPTH][WD];
    __shared__ __align__(16) float wouts[WD];
    __shared__ float bout_s;

    const int tid = threadIdx.x;

    for (int t = tid; t < WD * 8; t += TPB) {
        int c = t >> 3, i = t & 7;
        W0s[t] = (i < CMETA) ? W_lin_in[i * WD + c] : 0.0f;
    }
    for (int t = tid; t < DEPTH * WD * WD; t += TPB) {
        int d = t / (WD * WD); int r = t % (WD * WD); int i = r / WD, c = r % WD;
        Ws[(d * WD + c) * WD + i] = W_mlp[t];
    }
    for (int t = tid; t < BB * WD; t += TPB) {
        int bb = t / WD, c = t % WD;
        beffs[bb][c] = b_lin_in[c] + g_img_sum[bb][c] / g_img_cnt[bb];
    }
    if (tid < WD) wouts[tid] = W_out[tid];
    for (int t = tid; t < DEPTH * WD; t += TPB) bsd[t / WD][t % WD] = b_mlp[t];
    if (tid == 0) bout_s = b_out[0];
    __syncthreads();

    const int n_act = g_nact;
    const int slotA = blockIdx.x * PTSBLK + tid;

    if (slotA < n_act) {
        const int slotB = slotA + TPB;
        const bool validB = slotB < n_act;

        const int pA = g_idx[slotA];
        const int pB = validB ? g_idx[slotB] : pA;
        const int bA = pA / JK;
        const int bB = pB / JK;

        float x0[8], x1[8];
        {
            const float* m0 = metadata + (size_t)pA * CMETA;
            const float* m1 = metadata + (size_t)pB * CMETA;
#pragma unroll
            for (int i = 0; i < CMETA; i++) { x0[i] = m0[i]; x1[i] = m1[i]; }
            x0[6] = x0[7] = 0.0f; x1[6] = x1[7] = 0.0f;
        }

        float h0[WD], h1[WD], o0[WD], o1[WD];

#pragma unroll
        for (int c = 0; c < WD; c++) {
            float a0 = beffs[bA][c], a1 = beffs[bB][c];
            const float4* wr = (const float4*)&W0s[c * 8];
#pragma unroll
            for (int i4 = 0; i4 < 2; i4++) {
                float4 w = wr[i4];
                a0 = fmaf(x0[i4 * 4 + 0], w.x, a0);
                a0 = fmaf(x0[i4 * 4 + 1], w.y, a0);
                a0 = fmaf(x0[i4 * 4 + 2], w.z, a0);
                a0 = fmaf(x0[i4 * 4 + 3], w.w, a0);
                a1 = fmaf(x1[i4 * 4 + 0], w.x, a1);
                a1 = fmaf(x1[i4 * 4 + 1], w.y, a1);
                a1 = fmaf(x1[i4 * 4 + 2], w.z, a1);
                a1 = fmaf(x1[i4 * 4 + 3], w.w, a1);
            }
            h0[c] = a0; h1[c] = a1;
        }

#pragma unroll 1
        for (int d = 0; d < DEPTH; d++) {
            const float4* wl = (const float4*)&Ws[d * WD * WD];
#pragma unroll
            for (int c = 0; c < WD; c++) {
                float a0 = bsd[d][c], a1 = a0;
#pragma unroll
                for (int i4 = 0; i4 < 8; i4++) {
                    float4 w = wl[c * 8 + i4];
                    a0 = fmaf(h0[i4 * 4 + 0], w.x, a0);
                    a0 = fmaf(h0[i4 * 4 + 1], w.y, a0);
                    a0 = fmaf(h0[i4 * 4 + 2], w.z, a0);
                    a0 = fmaf(h0[i4 * 4 + 3], w.w, a0);
                    a1 = fmaf(h1[i4 * 4 + 0], w.x, a1);
                    a1 = fmaf(h1[i4 * 4 + 1], w.y, a1);
                    a1 = fmaf(h1[i4 * 4 + 2], w.z, a1);
                    a1 = fmaf(h1[i4 * 4 + 3], w.w, a1);
                }
                o0[c] = fmaxf(a0, 0.0f);
                o1[c] = fmaxf(a1, 0.0f);
            }
#pragma unroll
            for (int c = 0; c < WD; c++) { h0[c] = o0[c]; h1[c] = o1[c]; }
        }

        float r0 = bout_s, r1 = bout_s;
        const float4* wo = (const float4*)wouts;
#pragma unroll
        for (int i4 = 0; i4 < 8; i4++) {
            float4 w = wo[i4];
            r0 = fmaf(h0[i4 * 4 + 0], w.x, r0);
            r0 = fmaf(h0[i4 * 4 + 1], w.y, r0);
            r0 = fmaf(h0[i4 * 4 + 2], w.z, r0);
            r0 = fmaf(h0[i4 * 4 + 3], w.w, r0);
            r1 = fmaf(h1[i4 * 4 + 0], w.x, r1);
            r1 = fmaf(h1[i4 * 4 + 1], w.y, r1);
            r1 = fmaf(h1[i4 * 4 + 2], w.z, r1);
            r1 = fmaf(h1[i4 * 4 + 3], w.w, r1);
        }

        out[pA] = r0;
        if (validB) out[pB] = r1;
    }

    // replay-state reset: last block out (after ALL blocks have read g_nact)
    __syncthreads();
    if (tid == 0) {
        int old = atomicAdd(&g_done, 1);
        if (old == (int)gridDim.x - 1) {
            g_nact = 0;
            __threadfence();
            g_done = 0;
        }
    }
}

// ---------------------------------------------------------------------------
// Launch: sc (select ∥ compact) -> image -> main
// ---------------------------------------------------------------------------
extern "C" void kernel_launch(void* const* d_in, const int* in_sizes, int n_in,
                              void* d_out, int out_size)
{
    const float* Imodel   = (const float*)d_in[0];
    const float* Iobs     = (const float*)d_in[1];
    const float* metadata = (const float*)d_in[2];
    const void*  mask     = d_in[3];
    // d_in[4] = sample_size (always 32)
    const float* W_img_in = (const float*)d_in[5];
    const float* b_img_in = (const float*)d_in[6];
    const float* W_img    = (const float*)d_in[7];
    const float* b_img    = (const float*)d_in[8];
    const float* W_lin_in = (const float*)d_in[9];
    const float* b_lin_in = (const float*)d_in[10];
    const float* W_mlp    = (const float*)d_in[11];
    const float* b_mlp    = (const float*)d_in[12];
    const float* W_out    = (const float*)d_in[13];
    const float* b_out    = (const float*)d_in[14];
    float* out = (float*)d_out;

    k_sc<<<16 + NCOMPB, 256>>>(mask, out);
    k_image<<<BB * SS, ITB>>>(Imodel, Iobs, metadata, mask,
                              W_img_in, b_img_in, W_img, b_img);
    k_main<<<NMAINB, TPB>>>(metadata, W_lin_in, b_lin_in,
                            W_mlp, b_mlp, W_out, b_out, out);
}

// round 10
// speedup vs baseline: 1.7190x; 1.1230x over previous
#include <cuda_runtime.h>
#include <math.h>

// Problem constants
#define BB     16
#define JJ     256
#define KK     384
#define CMETA  6
#define CIN    8
#define WD     32
#define DEPTH  3
#define SS     32
#define JK     (JJ*KK)        // 98304
#define NPTS   (BB*JK)        // 1572864
#define TPB    128
#define PPT    4
#define PTSBLK (TPB*PPT)      // 512 slots per k_main block
#define NMAINB (NPTS/PTSBLK)  // 3072

// compact config (blocks 16.. in merged kernel)
#define CB   256
#define CPT  4
#define NCOMPB (NPTS/(CB*CPT))   // 1536

// Scratch (device globals)
__device__ int   g_fmt;
__device__ int   g_sel[BB][SS];
__device__ float g_img_sum[BB][WD];
__device__ float g_img_cnt[BB];
__device__ int   g_nact;
__device__ int   g_done;
__device__ int   g_idx[NPTS];

__device__ __forceinline__ bool mask_at(const void* m, int fmt, int i) {
    if (fmt == 0) return ((const unsigned char*)m)[i] != 0;
    if (fmt == 1) return ((const int*)m)[i] != 0;
    return ((const float*)m)[i] != 0.0f;
}

__device__ __forceinline__ int detect_fmt_block(const void* mask) {
    unsigned int v = ((const unsigned int*)mask)[threadIdx.x & 255];
    int all_int = __syncthreads_and(v <= 1u);
    int all_flt = __syncthreads_and(v == 0u || v == 0x3F800000u);
    return all_int ? 1 : (all_flt ? 2 : 0);
}

__device__ __forceinline__ unsigned int rotl32(unsigned int x, int r) {
    return (x << r) | (x >> (32 - r));
}

// ---------------------------------------------------------------------------
// Kernel 1 (merged): blocks [0,16) selection; blocks [16,..) compaction with
// block-aggregated atomics.
// ---------------------------------------------------------------------------
__global__ void __launch_bounds__(256) k_sc(const void* __restrict__ mask,
                                            float* __restrict__ out)
{
    const int fmt = detect_fmt_block(mask);
    const int tid = threadIdx.x;

    if (blockIdx.x >= 16) {
        const int cb = blockIdx.x - 16;
        const int lane = tid & 31;
        const int wid = tid >> 5;
        const unsigned int lt = (1u << lane) - 1u;
        const int base = cb * CB * CPT;

        bool act[CPT];
        unsigned int bal[CPT];
        int wcnt = 0;
#pragma unroll
        for (int r = 0; r < CPT; r++) {
            const int p = base + r * CB + tid;
            act[r] = mask_at(mask, fmt, p);
            bal[r] = __ballot_sync(0xFFFFFFFFu, act[r]);
            wcnt += __popc(bal[r]);
            if (!act[r]) out[p] = 0.0f;
        }

        __shared__ int wsum[8];
        __shared__ int bbase;
        if (lane == 0) wsum[wid] = wcnt;
        __syncthreads();
        if (tid == 0) {
            int tot = 0;
#pragma unroll
            for (int w = 0; w < 8; w++) { int c = wsum[w]; wsum[w] = tot; tot += c; }
            bbase = atomicAdd(&g_nact, tot);
        }
        __syncthreads();

        int off = bbase + wsum[wid];
#pragma unroll
        for (int r = 0; r < CPT; r++) {
            if (act[r]) g_idx[off + __popc(bal[r] & lt)] = base + r * CB + tid;
            off += __popc(bal[r]);
        }
        return;
    }

    // selection role
    const int b = blockIdx.x;
    const int j = tid;

    if (j == 0 && b == 0) g_fmt = fmt;
    if (j < WD) g_img_sum[b][j] = 0.0f;
    if (j == 0) g_img_cnt[b] = 0.0f;

    const int base = (b * JJ + j) * KK;
    bool alive = false;
    for (int k = 0; k < KK; k++) {
        if (mask_at(mask, fmt, base + k)) { alive = true; break; }
    }

    const unsigned int n = (unsigned int)(b * JJ + j);
    unsigned int x0 = 0u;
    unsigned int x1 = n;
    const unsigned int ks0 = 0u;
    const unsigned int ks1 = 42u;
    const unsigned int ks2 = 0x1BD11BDAu ^ 42u;
    x0 += ks0; x1 += ks1;
#define TF_ROUND(r) { x0 += x1; x1 = rotl32(x1, (r)); x1 ^= x0; }
    TF_ROUND(13) TF_ROUND(15) TF_ROUND(26) TF_ROUND(6)
    x0 += ks1; x1 += ks2 + 1u;
    TF_ROUND(17) TF_ROUND(29) TF_ROUND(16) TF_ROUND(24)
    x0 += ks2; x1 += ks0 + 2u;
    TF_ROUND(13) TF_ROUND(15) TF_ROUND(26) TF_ROUND(6)
    x0 += ks0; x1 += ks1 + 3u;
    TF_ROUND(17) TF_ROUND(29) TF_ROUND(16) TF_ROUND(24)
    x0 += ks1; x1 += ks2 + 4u;
    TF_ROUND(13) TF_ROUND(15) TF_ROUND(26) TF_ROUND(6)
    x0 += ks2; x1 += ks0 + 5u;
#undef TF_ROUND
    const unsigned int bits = x0 ^ x1;

    const unsigned int keyv = alive ? ((bits >> 9) | 0x80000000u) : 0u;

    __shared__ unsigned int sc[JJ];
    __shared__ int cnt;
    sc[j] = keyv;
    if (j == 0) cnt = 0;
    __syncthreads();

    int rank = 0;
    for (int t = 0; t < JJ; t++) {
        unsigned int s = sc[t];
        if (s > keyv || (s == keyv && t < j)) rank++;
    }
    if (rank < SS) {
        int slot = atomicAdd(&cnt, 1);
        g_sel[b][slot] = j;
    }
}

// ---------------------------------------------------------------------------
// Kernel 2: image branch; 4 sampled rows per block (weights amortized),
// 192 threads, 2 pts/thread per row.
// ---------------------------------------------------------------------------
#define ITB   192
#define RPB   4      // rows per block
__global__ void __launch_bounds__(ITB) k_image(
    const float* __restrict__ Imodel, const float* __restrict__ Iobs,
    const float* __restrict__ metadata, const void* __restrict__ mask,
    const float* __restrict__ W_img_in, const float* __restrict__ b_img_in,
    const float* __restrict__ W_img, const float* __restrict__ b_img)
{
    __shared__ __align__(16) float W0s[WD * CIN];
    __shared__ __align__(16) float Ws[DEPTH * WD * WD];
    __shared__ float bs0[WD];
    __shared__ float bsd[DEPTH][WD];

    const int tid = threadIdx.x;
    for (int t = tid; t < CIN * WD; t += ITB) {
        int i = t / WD, c = t % WD;
        W0s[c * CIN + i] = W_img_in[t];
    }
    for (int t = tid; t < DEPTH * WD * WD; t += ITB) {
        int d = t / (WD * WD); int r = t % (WD * WD); int i = r / WD, c = r % WD;
        Ws[(d * WD + c) * WD + i] = W_img[t];
    }
    for (int t = tid; t < WD; t += ITB) bs0[t] = b_img_in[t];
    for (int t = tid; t < DEPTH * WD; t += ITB) bsd[t / WD][t % WD] = b_img[t];
    __syncthreads();

    const int fmt = g_fmt;
    const int b = blockIdx.x / (SS / RPB);
    const int s0 = (blockIdx.x % (SS / RPB)) * RPB;

#pragma unroll 1
    for (int rr = 0; rr < RPB; rr++) {
        const int j = g_sel[b][s0 + rr];
        const int base = (b * JJ + j) * KK;
        const int pA = base + tid;
        const int pB = base + tid + ITB;

        float x0[CIN], x1[CIN];
        x0[0] = Imodel[pA]; x1[0] = Imodel[pB];
        x0[1] = Iobs[pA];   x1[1] = Iobs[pB];
        {
            const float* m0 = metadata + (size_t)pA * CMETA;
            const float* m1 = metadata + (size_t)pB * CMETA;
#pragma unroll
            for (int i = 0; i < CMETA; i++) { x0[2 + i] = m0[i]; x1[2 + i] = m1[i]; }
        }

        float h0[WD], h1[WD], o0[WD], o1[WD];

#pragma unroll
        for (int c = 0; c < WD; c++) {
            float a0 = bs0[c], a1 = a0;
            const float4* wr = (const float4*)&W0s[c * CIN];
#pragma unroll
            for (int i4 = 0; i4 < 2; i4++) {
                float4 w = wr[i4];
                a0 = fmaf(x0[i4 * 4 + 0], w.x, a0);
                a0 = fmaf(x0[i4 * 4 + 1], w.y, a0);
                a0 = fmaf(x0[i4 * 4 + 2], w.z, a0);
                a0 = fmaf(x0[i4 * 4 + 3], w.w, a0);
                a1 = fmaf(x1[i4 * 4 + 0], w.x, a1);
                a1 = fmaf(x1[i4 * 4 + 1], w.y, a1);
                a1 = fmaf(x1[i4 * 4 + 2], w.z, a1);
                a1 = fmaf(x1[i4 * 4 + 3], w.w, a1);
            }
            h0[c] = a0; h1[c] = a1;
        }

#pragma unroll 1
        for (int d = 0; d < DEPTH; d++) {
            const float4* wl = (const float4*)&Ws[d * WD * WD];
#pragma unroll
            for (int c = 0; c < WD; c++) {
                float a0 = bsd[d][c], a1 = a0;
#pragma unroll
                for (int i4 = 0; i4 < 8; i4++) {
                    float4 w = wl[c * 8 + i4];
                    a0 = fmaf(h0[i4 * 4 + 0], w.x, a0);
                    a0 = fmaf(h0[i4 * 4 + 1], w.y, a0);
                    a0 = fmaf(h0[i4 * 4 + 2], w.z, a0);
                    a0 = fmaf(h0[i4 * 4 + 3], w.w, a0);
                    a1 = fmaf(h1[i4 * 4 + 0], w.x, a1);
                    a1 = fmaf(h1[i4 * 4 + 1], w.y, a1);
                    a1 = fmaf(h1[i4 * 4 + 2], w.z, a1);
                    a1 = fmaf(h1[i4 * 4 + 3], w.w, a1);
                }
                o0[c] = fmaxf(a0, 0.0f);
                o1[c] = fmaxf(a1, 0.0f);
            }
#pragma unroll
            for (int c = 0; c < WD; c++) { h0[c] = o0[c]; h1[c] = o1[c]; }
        }

        const float m0 = mask_at(mask, fmt, pA) ? 1.0f : 0.0f;
        const float m1 = mask_at(mask, fmt, pB) ? 1.0f : 0.0f;

#pragma unroll
        for (int c = 0; c < WD; c++) {
            float v = m0 * h0[c] + m1 * h1[c];
#pragma unroll
            for (int o = 16; o > 0; o >>= 1) v += __shfl_xor_sync(0xFFFFFFFFu, v, o);
            if ((tid & 31) == 0) atomicAdd(&g_img_sum[b][c], v);
        }
        {
            float v = m0 + m1;
#pragma unroll
            for (int o = 16; o > 0; o >>= 1) v += __shfl_xor_sync(0xFFFFFFFFu, v, o);
            if ((tid & 31) == 0) atomicAdd(&g_img_cnt[b], v);
        }
    }
}

// ---------------------------------------------------------------------------
// Kernel 3: main branch over compacted points. PPT=4, float4 weights.
// ---------------------------------------------------------------------------
__global__ void __launch_bounds__(TPB, 2) k_main(
    const float* __restrict__ metadata,
    const float* __restrict__ W_lin_in, const float* __restrict__ b_lin_in,
    const float* __restrict__ W_mlp, const float* __restrict__ b_mlp,
    const float* __restrict__ W_out, const float* __restrict__ b_out,
    float* __restrict__ out)
{
    __shared__ __align__(16) float W0s[WD * 8];
    __shared__ __align__(16) float Ws[DEPTH * WD * WD];
    __shared__ float beffs[BB][WD];
    __shared__ float bsd[DEPTH][WD];
    __shared__ __align__(16) float wouts[WD];
    __shared__ float bout_s;

    const int tid = threadIdx.x;

    for (int t = tid; t < WD * 8; t += TPB) {
        int c = t >> 3, i = t & 7;
        W0s[t] = (i < CMETA) ? W_lin_in[i * WD + c] : 0.0f;
    }
    for (int t = tid; t < DEPTH * WD * WD; t += TPB) {
        int d = t / (WD * WD); int r = t % (WD * WD); int i = r / WD, c = r % WD;
        Ws[(d * WD + c) * WD + i] = W_mlp[t];
    }
    for (int t = tid; t < BB * WD; t += TPB) {
        int bb = t / WD, c = t % WD;
        beffs[bb][c] = b_lin_in[c] + g_img_sum[bb][c] / g_img_cnt[bb];
    }
    if (tid < WD) wouts[tid] = W_out[tid];
    for (int t = tid; t < DEPTH * WD; t += TPB) bsd[t / WD][t % WD] = b_mlp[t];
    if (tid == 0) bout_s = b_out[0];
    __syncthreads();

    const int n_act = g_nact;
    const int slot0 = blockIdx.x * PTSBLK + tid;

    if (slot0 < n_act) {
        int pp[PPT];
        int bb[PPT];
        bool valid[PPT];
#pragma unroll
        for (int r = 0; r < PPT; r++) {
            int s = slot0 + r * TPB;
            valid[r] = s < n_act;
            pp[r] = valid[r] ? g_idx[s] : g_idx[slot0];
            bb[r] = pp[r] / JK;
        }

        float x[PPT][8];
#pragma unroll
        for (int r = 0; r < PPT; r++) {
            const float* mp = metadata + (size_t)pp[r] * CMETA;
#pragma unroll
            for (int i = 0; i < CMETA; i++) x[r][i] = mp[i];
            x[r][6] = x[r][7] = 0.0f;
        }

        float h[PPT][WD], o[PPT][WD];

        // input layer
#pragma unroll
        for (int c = 0; c < WD; c++) {
            float a[PPT];
#pragma unroll
            for (int r = 0; r < PPT; r++) a[r] = beffs[bb[r]][c];
            const float4* wr = (const float4*)&W0s[c * 8];
#pragma unroll
            for (int i4 = 0; i4 < 2; i4++) {
                float4 w = wr[i4];
#pragma unroll
                for (int r = 0; r < PPT; r++) {
                    a[r] = fmaf(x[r][i4 * 4 + 0], w.x, a[r]);
                    a[r] = fmaf(x[r][i4 * 4 + 1], w.y, a[r]);
                    a[r] = fmaf(x[r][i4 * 4 + 2], w.z, a[r]);
                    a[r] = fmaf(x[r][i4 * 4 + 3], w.w, a[r]);
                }
            }
#pragma unroll
            for (int r = 0; r < PPT; r++) h[r][c] = a[r];
        }

        // hidden layers
#pragma unroll 1
        for (int d = 0; d < DEPTH; d++) {
            const float4* wl = (const float4*)&Ws[d * WD * WD];
#pragma unroll
            for (int c = 0; c < WD; c++) {
                float a[PPT];
#pragma unroll
                for (int r = 0; r < PPT; r++) a[r] = bsd[d][c];
#pragma unroll
                for (int i4 = 0; i4 < 8; i4++) {
                    float4 w = wl[c * 8 + i4];
#pragma unroll
                    for (int r = 0; r < PPT; r++) {
                        a[r] = fmaf(h[r][i4 * 4 + 0], w.x, a[r]);
                        a[r] = fmaf(h[r][i4 * 4 + 1], w.y, a[r]);
                        a[r] = fmaf(h[r][i4 * 4 + 2], w.z, a[r]);
                        a[r] = fmaf(h[r][i4 * 4 + 3], w.w, a[r]);
                    }
                }
#pragma unroll
                for (int r = 0; r < PPT; r++) o[r][c] = fmaxf(a[r], 0.0f);
            }
#pragma unroll
            for (int c = 0; c < WD; c++)
#pragma unroll
                for (int r = 0; r < PPT; r++) h[r][c] = o[r][c];
        }

        // output layer
        float res[PPT];
#pragma unroll
        for (int r = 0; r < PPT; r++) res[r] = bout_s;
        const float4* wo = (const float4*)wouts;
#pragma unroll
        for (int i4 = 0; i4 < 8; i4++) {
            float4 w = wo[i4];
#pragma unroll
            for (int r = 0; r < PPT; r++) {
                res[r] = fmaf(h[r][i4 * 4 + 0], w.x, res[r]);
                res[r] = fmaf(h[r][i4 * 4 + 1], w.y, res[r]);
                res[r] = fmaf(h[r][i4 * 4 + 2], w.z, res[r]);
                res[r] = fmaf(h[r][i4 * 4 + 3], w.w, res[r]);
            }
        }

#pragma unroll
        for (int r = 0; r < PPT; r++)
            if (valid[r]) out[pp[r]] = res[r];
    }

    // replay-state reset: last block out
    __syncthreads();
    if (tid == 0) {
        int old = atomicAdd(&g_done, 1);
        if (old == (int)gridDim.x - 1) {
            g_nact = 0;
            __threadfence();
            g_done = 0;
        }
    }
}

// ---------------------------------------------------------------------------
extern "C" void kernel_launch(void* const* d_in, const int* in_sizes, int n_in,
                              void* d_out, int out_size)
{
    const float* Imodel   = (const float*)d_in[0];
    const float* Iobs     = (const float*)d_in[1];
    const float* metadata = (const float*)d_in[2];
    const void*  mask     = d_in[3];
    const float* W_img_in = (const float*)d_in[5];
    const float* b_img_in = (const float*)d_in[6];
    const float* W_img    = (const float*)d_in[7];
    const float* b_img    = (const float*)d_in[8];
    const float* W_lin_in = (const float*)d_in[9];
    const float* b_lin_in = (const float*)d_in[10];
    const float* W_mlp    = (const float*)d_in[11];
    const float* b_mlp    = (const float*)d_in[12];
    const float* W_out    = (const float*)d_in[13];
    const float* b_out    = (const float*)d_in[14];
    float* out = (float*)d_out;

    k_sc<<<16 + NCOMPB, 256>>>(mask, out);
    k_image<<<BB * (SS / RPB), ITB>>>(Imodel, Iobs, metadata, mask,
                                      W_img_in, b_img_in, W_img, b_img);
    k_main<<<NMAINB, TPB>>>(metadata, W_lin_in, b_lin_in,
                            W_mlp, b_mlp, W_out, b_out, out);
}

// round 11
// speedup vs baseline: 2.0026x; 1.1650x over previous
#include <cuda_runtime.h>
#include <math.h>
#include <stdint.h>

// Problem constants
#define BB     16
#define JJ     256
#define KK     384
#define CMETA  6
#define CIN    8
#define WD     32
#define DEPTH  3
#define SS     32
#define JK     (JJ*KK)        // 98304
#define NPTS   (BB*JK)        // 1572864

// tensor k_main config
#define MT_TPB   128          // 4 warps
#define MT_ROWS  128          // rows per iteration (1 per thread)
#define MT_ITERS 4
#define MT_PTSBLK (MT_ROWS*MT_ITERS)   // 512
#define NMAINB  (NPTS/MT_PTSBLK)       // 3072

// compact config (blocks 16.. in merged kernel)
#define CB   256
#define CPT  4
#define NCOMPB (NPTS/(CB*CPT))   // 1536

// dynamic smem layout (uints/floats), see k_main
#define WF_U32    (3*4*2*2*32*4)   // 12288
#define WF0_U32   (2*2*32*4)       // 512
#define HROW_F32  (4*32*36)        // 4608
#define SMEM_BYTES ((WF_U32 + WF0_U32)*4 + (HROW_F32 + BB*WD + DEPTH*WD + WD + 4)*4 + 2*128*4 + 256)

// Scratch (device globals)
__device__ int   g_fmt;
__device__ int   g_sel[BB][SS];
__device__ float g_img_sum[BB][WD];
__device__ float g_img_cnt[BB];
__device__ int   g_nact;
__device__ int   g_done;
__device__ int   g_idx[NPTS];

__device__ __forceinline__ bool mask_at(const void* m, int fmt, int i) {
    if (fmt == 0) return ((const unsigned char*)m)[i] != 0;
    if (fmt == 1) return ((const int*)m)[i] != 0;
    return ((const float*)m)[i] != 0.0f;
}

__device__ __forceinline__ int detect_fmt_block(const void* mask) {
    unsigned int v = ((const unsigned int*)mask)[threadIdx.x & 255];
    int all_int = __syncthreads_and(v <= 1u);
    int all_flt = __syncthreads_and(v == 0u || v == 0x3F800000u);
    return all_int ? 1 : (all_flt ? 2 : 0);
}

__device__ __forceinline__ unsigned int rotl32(unsigned int x, int r) {
    return (x << r) | (x >> (32 - r));
}

__device__ __forceinline__ uint32_t f2tf32(float f) {
    uint32_t u;
    asm("cvt.rna.tf32.f32 %0, %1;" : "=r"(u) : "f"(f));
    return u;
}
__device__ __forceinline__ void split_tf32(float v, uint32_t& hi, uint32_t& lo) {
    hi = f2tf32(v);
    lo = f2tf32(v - __uint_as_float(hi));
}
__device__ __forceinline__ void mma_tf32(float c[4],
                                         uint32_t a0, uint32_t a1, uint32_t a2, uint32_t a3,
                                         uint32_t b0, uint32_t b1) {
    asm("mma.sync.aligned.m16n8k8.row.col.f32.tf32.tf32.f32 "
        "{%0,%1,%2,%3},{%4,%5,%6,%7},{%8,%9},{%0,%1,%2,%3};"
        : "+f"(c[0]), "+f"(c[1]), "+f"(c[2]), "+f"(c[3])
        : "r"(a0), "r"(a1), "r"(a2), "r"(a3), "r"(b0), "r"(b1));
}

// ---------------------------------------------------------------------------
// Kernel 1 (merged): blocks [0,16) selection; blocks [16,..) compaction.
// ---------------------------------------------------------------------------
__global__ void __launch_bounds__(256) k_sc(const void* __restrict__ mask,
                                            float* __restrict__ out)
{
    const int fmt = detect_fmt_block(mask);
    const int tid = threadIdx.x;

    if (blockIdx.x >= 16) {
        const int cb = blockIdx.x - 16;
        const int lane = tid & 31;
        const int wid = tid >> 5;
        const unsigned int lt = (1u << lane) - 1u;
        const int base = cb * CB * CPT;

        bool act[CPT];
        unsigned int bal[CPT];
        int wcnt = 0;
#pragma unroll
        for (int r = 0; r < CPT; r++) {
            const int p = base + r * CB + tid;
            act[r] = mask_at(mask, fmt, p);
            bal[r] = __ballot_sync(0xFFFFFFFFu, act[r]);
            wcnt += __popc(bal[r]);
            if (!act[r]) out[p] = 0.0f;
        }

        __shared__ int wsum[8];
        __shared__ int bbase;
        if (lane == 0) wsum[wid] = wcnt;
        __syncthreads();
        if (tid == 0) {
            int tot = 0;
#pragma unroll
            for (int w = 0; w < 8; w++) { int c = wsum[w]; wsum[w] = tot; tot += c; }
            bbase = atomicAdd(&g_nact, tot);
        }
        __syncthreads();

        int off = bbase + wsum[wid];
#pragma unroll
        for (int r = 0; r < CPT; r++) {
            if (act[r]) g_idx[off + __popc(bal[r] & lt)] = base + r * CB + tid;
            off += __popc(bal[r]);
        }
        return;
    }

    // selection role
    const int b = blockIdx.x;
    const int j = tid;

    if (j == 0 && b == 0) g_fmt = fmt;
    if (j < WD) g_img_sum[b][j] = 0.0f;
    if (j == 0) g_img_cnt[b] = 0.0f;

    const int base = (b * JJ + j) * KK;
    bool alive = false;
    for (int k = 0; k < KK; k++) {
        if (mask_at(mask, fmt, base + k)) { alive = true; break; }
    }

    const unsigned int n = (unsigned int)(b * JJ + j);
    unsigned int x0 = 0u;
    unsigned int x1 = n;
    const unsigned int ks0 = 0u;
    const unsigned int ks1 = 42u;
    const unsigned int ks2 = 0x1BD11BDAu ^ 42u;
    x0 += ks0; x1 += ks1;
#define TF_ROUND(r) { x0 += x1; x1 = rotl32(x1, (r)); x1 ^= x0; }
    TF_ROUND(13) TF_ROUND(15) TF_ROUND(26) TF_ROUND(6)
    x0 += ks1; x1 += ks2 + 1u;
    TF_ROUND(17) TF_ROUND(29) TF_ROUND(16) TF_ROUND(24)
    x0 += ks2; x1 += ks0 + 2u;
    TF_ROUND(13) TF_ROUND(15) TF_ROUND(26) TF_ROUND(6)
    x0 += ks0; x1 += ks1 + 3u;
    TF_ROUND(17) TF_ROUND(29) TF_ROUND(16) TF_ROUND(24)
    x0 += ks1; x1 += ks2 + 4u;
    TF_ROUND(13) TF_ROUND(15) TF_ROUND(26) TF_ROUND(6)
    x0 += ks2; x1 += ks0 + 5u;
#undef TF_ROUND
    const unsigned int bits = x0 ^ x1;

    const unsigned int keyv = alive ? ((bits >> 9) | 0x80000000u) : 0u;

    __shared__ unsigned int sc[JJ];
    __shared__ int cnt;
    sc[j] = keyv;
    if (j == 0) cnt = 0;
    __syncthreads();

    int rank = 0;
    for (int t = 0; t < JJ; t++) {
        unsigned int s = sc[t];
        if (s > keyv || (s == keyv && t < j)) rank++;
    }
    if (rank < SS) {
        int slot = atomicAdd(&cnt, 1);
        g_sel[b][slot] = j;
    }
}

// ---------------------------------------------------------------------------
// Kernel 2: image branch; 4 sampled rows per block, float4 weights, 2 pts/thr.
// ---------------------------------------------------------------------------
#define ITB   192
#define RPB   4
__global__ void __launch_bounds__(ITB) k_image(
    const float* __restrict__ Imodel, const float* __restrict__ Iobs,
    const float* __restrict__ metadata, const void* __restrict__ mask,
    const float* __restrict__ W_img_in, const float* __restrict__ b_img_in,
    const float* __restrict__ W_img, const float* __restrict__ b_img)
{
    __shared__ __align__(16) float W0s[WD * CIN];
    __shared__ __align__(16) float Ws[DEPTH * WD * WD];
    __shared__ float bs0[WD];
    __shared__ float bsd[DEPTH][WD];

    const int tid = threadIdx.x;
    for (int t = tid; t < CIN * WD; t += ITB) {
        int i = t / WD, c = t % WD;
        W0s[c * CIN + i] = W_img_in[t];
    }
    for (int t = tid; t < DEPTH * WD * WD; t += ITB) {
        int d = t / (WD * WD); int r = t % (WD * WD); int i = r / WD, c = r % WD;
        Ws[(d * WD + c) * WD + i] = W_img[t];
    }
    for (int t = tid; t < WD; t += ITB) bs0[t] = b_img_in[t];
    for (int t = tid; t < DEPTH * WD; t += ITB) bsd[t / WD][t % WD] = b_img[t];
    __syncthreads();

    const int fmt = g_fmt;
    const int b = blockIdx.x / (SS / RPB);
    const int s0 = (blockIdx.x % (SS / RPB)) * RPB;

#pragma unroll 1
    for (int rr = 0; rr < RPB; rr++) {
        const int j = g_sel[b][s0 + rr];
        const int base = (b * JJ + j) * KK;
        const int pA = base + tid;
        const int pB = base + tid + ITB;

        float x0[CIN], x1[CIN];
        x0[0] = Imodel[pA]; x1[0] = Imodel[pB];
        x0[1] = Iobs[pA];   x1[1] = Iobs[pB];
        {
            const float* m0 = metadata + (size_t)pA * CMETA;
            const float* m1 = metadata + (size_t)pB * CMETA;
#pragma unroll
            for (int i = 0; i < CMETA; i++) { x0[2 + i] = m0[i]; x1[2 + i] = m1[i]; }
        }

        float h0[WD], h1[WD], o0[WD], o1[WD];

#pragma unroll
        for (int c = 0; c < WD; c++) {
            float a0 = bs0[c], a1 = a0;
            const float4* wr = (const float4*)&W0s[c * CIN];
#pragma unroll
            for (int i4 = 0; i4 < 2; i4++) {
                float4 w = wr[i4];
                a0 = fmaf(x0[i4 * 4 + 0], w.x, a0);
                a0 = fmaf(x0[i4 * 4 + 1], w.y, a0);
                a0 = fmaf(x0[i4 * 4 + 2], w.z, a0);
                a0 = fmaf(x0[i4 * 4 + 3], w.w, a0);
                a1 = fmaf(x1[i4 * 4 + 0], w.x, a1);
                a1 = fmaf(x1[i4 * 4 + 1], w.y, a1);
                a1 = fmaf(x1[i4 * 4 + 2], w.z, a1);
                a1 = fmaf(x1[i4 * 4 + 3], w.w, a1);
            }
            h0[c] = a0; h1[c] = a1;
        }

#pragma unroll 1
        for (int d = 0; d < DEPTH; d++) {
            const float4* wl = (const float4*)&Ws[d * WD * WD];
#pragma unroll
            for (int c = 0; c < WD; c++) {
                float a0 = bsd[d][c], a1 = a0;
#pragma unroll
                for (int i4 = 0; i4 < 8; i4++) {
                    float4 w = wl[c * 8 + i4];
                    a0 = fmaf(h0[i4 * 4 + 0], w.x, a0);
                    a0 = fmaf(h0[i4 * 4 + 1], w.y, a0);
                    a0 = fmaf(h0[i4 * 4 + 2], w.z, a0);
                    a0 = fmaf(h0[i4 * 4 + 3], w.w, a0);
                    a1 = fmaf(h1[i4 * 4 + 0], w.x, a1);
                    a1 = fmaf(h1[i4 * 4 + 1], w.y, a1);
                    a1 = fmaf(h1[i4 * 4 + 2], w.z, a1);
                    a1 = fmaf(h1[i4 * 4 + 3], w.w, a1);
                }
                o0[c] = fmaxf(a0, 0.0f);
                o1[c] = fmaxf(a1, 0.0f);
            }
#pragma unroll
            for (int c = 0; c < WD; c++) { h0[c] = o0[c]; h1[c] = o1[c]; }
        }

        const float m0 = mask_at(mask, fmt, pA) ? 1.0f : 0.0f;
        const float m1 = mask_at(mask, fmt, pB) ? 1.0f : 0.0f;

#pragma unroll
        for (int c = 0; c < WD; c++) {
            float v = m0 * h0[c] + m1 * h1[c];
#pragma unroll
            for (int o = 16; o > 0; o >>= 1) v += __shfl_xor_sync(0xFFFFFFFFu, v, o);
            if ((tid & 31) == 0) atomicAdd(&g_img_sum[b][c], v);
        }
        {
            float v = m0 + m1;
#pragma unroll
            for (int o = 16; o > 0; o >>= 1) v += __shfl_xor_sync(0xFFFFFFFFu, v, o);
            if ((tid & 31) == 0) atomicAdd(&g_img_cnt[b], v);
        }
    }
}

// ---------------------------------------------------------------------------
// Kernel 3: main branch on TENSOR CORES (tf32 mma, 3-pass hi/lo split).
// 4 warps/block, 32 rows/warp/iter, 4 iters = 512 points/block.
// Activations round-trip through padded SMEM between layers.
// ---------------------------------------------------------------------------
__global__ void __launch_bounds__(MT_TPB, 3) k_main(
    const float* __restrict__ metadata,
    const float* __restrict__ W_lin_in, const float* __restrict__ b_lin_in,
    const float* __restrict__ W_mlp, const float* __restrict__ b_mlp,
    const float* __restrict__ W_out, const float* __restrict__ b_out,
    float* __restrict__ out)
{
    extern __shared__ __align__(16) unsigned char dynsmem[];
    uint32_t* Wf   = (uint32_t*)dynsmem;          // [d][kt][reg][hl][lane][nt]
    uint32_t* Wf0  = Wf + WF_U32;                 // [reg][hl][lane][nt]
    float* hrow    = (float*)(Wf0 + WF0_U32);     // [4][32][36]
    float* beffs   = hrow + HROW_F32;             // [16][32]
    float* bsd     = beffs + BB * WD;             // [3][32]
    float* wout_s  = bsd + DEPTH * WD;            // [32]
    float* bout_s  = wout_s + WD;                 // [1]
    int*   xb      = (int*)(bout_s + 4);          // [4][32]
    int*   xp      = xb + 128;                    // [4][32]

    const int tid = threadIdx.x;

    // ---- weight fragment precompute (hi/lo tf32 split) ----
    for (int t = tid; t < 3 * 4 * 2 * 32 * 4; t += MT_TPB) {     // 1536
        int nt = t & 3, lane = (t >> 2) & 31, reg = (t >> 7) & 1;
        int kt = (t >> 8) & 3, d = t >> 10;
        int k = (lane & 3) + 4 * reg + 8 * kt;
        int nn = (lane >> 2) + 8 * nt;
        float w = W_mlp[(d * WD + k) * WD + nn];
        uint32_t hi, lo; split_tf32(w, hi, lo);
        int basei = (((d * 4 + kt) * 2 + reg) * 2) * 128 + lane * 4 + nt;
        Wf[basei] = hi;
        Wf[basei + 128] = lo;
    }
    for (int t = tid; t < 2 * 32 * 4; t += MT_TPB) {             // 256
        int nt = t & 3, lane = (t >> 2) & 31, reg = t >> 7;
        int k = (lane & 3) + 4 * reg;
        int nn = (lane >> 2) + 8 * nt;
        float w = (k < CMETA) ? W_lin_in[k * WD + nn] : 0.0f;
        uint32_t hi, lo; split_tf32(w, hi, lo);
        Wf0[(reg * 2) * 128 + lane * 4 + nt] = hi;
        Wf0[(reg * 2 + 1) * 128 + lane * 4 + nt] = lo;
    }
    for (int t = tid; t < BB * WD; t += MT_TPB) {
        int bb = t / WD, c = t % WD;
        beffs[t] = b_lin_in[c] + g_img_sum[bb][c] / g_img_cnt[bb];
    }
    for (int t = tid; t < DEPTH * WD; t += MT_TPB) bsd[t] = b_mlp[t];
    if (tid < WD) wout_s[tid] = W_out[tid];
    if (tid == 0) bout_s[0] = b_out[0];
    __syncthreads();

    const int n_act = g_nact;
    const int w = tid >> 5;
    const int lane = tid & 31;
    const int g = lane >> 2;
    const int q = lane & 3;
    const int blkbase = blockIdx.x * MT_PTSBLK;

    // per-thread wout values for its C columns: wo[nt*2 + parity]
    float wo[8];
#pragma unroll
    for (int nt = 0; nt < 4; nt++) {
        wo[nt * 2 + 0] = wout_s[8 * nt + 2 * q + 0];
        wo[nt * 2 + 1] = wout_s[8 * nt + 2 * q + 1];
    }
    const float boutv = bout_s[0];
    float* myrows = hrow + w * 32 * 36;    // warp-private region
    int* myxb = xb + w * 32;
    int* myxp = xp + w * 32;

    if (blkbase < n_act) {
#pragma unroll 1
        for (int it = 0; it < MT_ITERS; it++) {
            if (blkbase + it * MT_ROWS >= n_act) break;
            const int slot = blkbase + it * MT_ROWS + tid;
            const bool valid = slot < n_act;
            const int p = valid ? g_idx[slot] : 0;

            __syncwarp();
            // stage this thread's row
            {
                const float* mp = metadata + (size_t)p * CMETA;
                float* xr = myrows + lane * 36;
#pragma unroll
                for (int i = 0; i < CMETA; i++) xr[i] = mp[i];
                xr[6] = 0.0f; xr[7] = 0.0f;
                myxb[lane] = p / JK;
                myxp[lane] = valid ? p : -1;
            }
            __syncwarp();

            const int b4[4] = { myxb[g], myxb[g + 8], myxb[g + 16], myxb[g + 24] };

            // ---- input layer (K=8, 1 ktile): C = X @ W_in ----
            float cc[2][4][4];
#pragma unroll
            for (int mt = 0; mt < 2; mt++)
#pragma unroll
                for (int nt = 0; nt < 4; nt++)
#pragma unroll
                    for (int r = 0; r < 4; r++) cc[mt][nt][r] = 0.0f;

            {
                uint32_t ah[2][4], al[2][4];
#pragma unroll
                for (int mt = 0; mt < 2; mt++) {
                    const int R = 16 * mt;
                    split_tf32(myrows[(R + g) * 36 + q],          ah[mt][0], al[mt][0]);
                    split_tf32(myrows[(R + g + 8) * 36 + q],      ah[mt][1], al[mt][1]);
                    split_tf32(myrows[(R + g) * 36 + q + 4],      ah[mt][2], al[mt][2]);
                    split_tf32(myrows[(R + g + 8) * 36 + q + 4],  ah[mt][3], al[mt][3]);
                }
                uint4 b0h = *(const uint4*)&Wf0[0 * 128 + lane * 4];   // reg0 hi
                uint4 b0l = *(const uint4*)&Wf0[1 * 128 + lane * 4];   // reg0 lo
                uint4 b1h = *(const uint4*)&Wf0[2 * 128 + lane * 4];   // reg1 hi
                uint4 b1l = *(const uint4*)&Wf0[3 * 128 + lane * 4];   // reg1 lo
                uint32_t B0H[4] = {b0h.x, b0h.y, b0h.z, b0h.w};
                uint32_t B0L[4] = {b0l.x, b0l.y, b0l.z, b0l.w};
                uint32_t B1H[4] = {b1h.x, b1h.y, b1h.z, b1h.w};
                uint32_t B1L[4] = {b1l.x, b1l.y, b1l.z, b1l.w};
#pragma unroll
                for (int mt = 0; mt < 2; mt++)
#pragma unroll
                    for (int nt = 0; nt < 4; nt++) {
                        mma_tf32(cc[mt][nt], ah[mt][0], ah[mt][1], ah[mt][2], ah[mt][3], B0H[nt], B1H[nt]);
                        mma_tf32(cc[mt][nt], al[mt][0], al[mt][1], al[mt][2], al[mt][3], B0H[nt], B1H[nt]);
                        mma_tf32(cc[mt][nt], ah[mt][0], ah[mt][1], ah[mt][2], ah[mt][3], B0L[nt], B1L[nt]);
                    }
            }

            // bias (beff by batch), no relu; write to hrow
            __syncwarp();
#pragma unroll
            for (int mt = 0; mt < 2; mt++)
#pragma unroll
                for (int nt = 0; nt < 4; nt++)
#pragma unroll
                    for (int r = 0; r < 4; r++) {
                        int rowl = 16 * mt + g + 8 * (r >> 1);
                        int col = 8 * nt + 2 * q + (r & 1);
                        int bi = b4[mt * 2 + (r >> 1)];
                        myrows[rowl * 36 + col] = cc[mt][nt][r] + beffs[bi * WD + col];
                    }
            __syncwarp();

            // ---- hidden layers ----
            float acc[4] = {0.0f, 0.0f, 0.0f, 0.0f};
#pragma unroll
            for (int d = 0; d < DEPTH; d++) {
#pragma unroll
                for (int mt = 0; mt < 2; mt++)
#pragma unroll
                    for (int nt = 0; nt < 4; nt++)
#pragma unroll
                        for (int r = 0; r < 4; r++) cc[mt][nt][r] = 0.0f;

#pragma unroll
                for (int kt = 0; kt < 4; kt++) {
                    uint32_t ah[2][4], al[2][4];
                    const int kc = 8 * kt;
#pragma unroll
                    for (int mt = 0; mt < 2; mt++) {
                        const int R = 16 * mt;
                        split_tf32(myrows[(R + g) * 36 + kc + q],         ah[mt][0], al[mt][0]);
                        split_tf32(myrows[(R + g + 8) * 36 + kc + q],     ah[mt][1], al[mt][1]);
                        split_tf32(myrows[(R + g) * 36 + kc + q + 4],     ah[mt][2], al[mt][2]);
                        split_tf32(myrows[(R + g + 8) * 36 + kc + q + 4], ah[mt][3], al[mt][3]);
                    }
                    const int wbase = ((d * 4 + kt) * 4) * 128 + lane * 4;
                    uint4 b0h = *(const uint4*)&Wf[wbase];            // reg0 hi
                    uint4 b0l = *(const uint4*)&Wf[wbase + 128];      // reg0 lo
                    uint4 b1h = *(const uint4*)&Wf[wbase + 256];      // reg1 hi
                    uint4 b1l = *(const uint4*)&Wf[wbase + 384];      // reg1 lo
                    uint32_t B0H[4] = {b0h.x, b0h.y, b0h.z, b0h.w};
                    uint32_t B0L[4] = {b0l.x, b0l.y, b0l.z, b0l.w};
                    uint32_t B1H[4] = {b1h.x, b1h.y, b1h.z, b1h.w};
                    uint32_t B1L[4] = {b1l.x, b1l.y, b1l.z, b1l.w};
#pragma unroll
                    for (int mt = 0; mt < 2; mt++)
#pragma unroll
                        for (int nt = 0; nt < 4; nt++) {
                            mma_tf32(cc[mt][nt], ah[mt][0], ah[mt][1], ah[mt][2], ah[mt][3], B0H[nt], B1H[nt]);
                            mma_tf32(cc[mt][nt], al[mt][0], al[mt][1], al[mt][2], al[mt][3], B0H[nt], B1H[nt]);
                            mma_tf32(cc[mt][nt], ah[mt][0], ah[mt][1], ah[mt][2], ah[mt][3], B0L[nt], B1L[nt]);
                        }
                }

                // bias + relu; intermediate layers -> hrow, last layer -> output acc
                __syncwarp();
#pragma unroll
                for (int mt = 0; mt < 2; mt++)
#pragma unroll
                    for (int nt = 0; nt < 4; nt++)
#pragma unroll
                        for (int r = 0; r < 4; r++) {
                            int col = 8 * nt + 2 * q + (r & 1);
                            float hv = fmaxf(cc[mt][nt][r] + bsd[d * WD + col], 0.0f);
                            if (d < DEPTH - 1) {
                                int rowl = 16 * mt + g + 8 * (r >> 1);
                                myrows[rowl * 36 + col] = hv;
                            } else {
                                acc[mt * 2 + (r >> 1)] = fmaf(hv, wo[nt * 2 + (r & 1)], acc[mt * 2 + (r >> 1)]);
                            }
                        }
                __syncwarp();
            }

            // ---- output reduce across the 4-lane column group ----
#pragma unroll
            for (int jj = 0; jj < 4; jj++) {
                acc[jj] += __shfl_xor_sync(0xFFFFFFFFu, acc[jj], 1);
                acc[jj] += __shfl_xor_sync(0xFFFFFFFFu, acc[jj], 2);
            }
            if (q == 0) {
#pragma unroll
                for (int jj = 0; jj < 4; jj++) {
                    int rowl = 16 * (jj >> 1) + g + 8 * (jj & 1);
                    int pt = myxp[rowl];
                    if (pt >= 0) out[pt] = acc[jj] + boutv;
                }
            }
        }
    }

    // replay-state reset: last block out
    __syncthreads();
    if (tid == 0) {
        int old = atomicAdd(&g_done, 1);
        if (old == (int)gridDim.x - 1) {
            g_nact = 0;
            __threadfence();
            g_done = 0;
        }
    }
}

// ---------------------------------------------------------------------------
extern "C" void kernel_launch(void* const* d_in, const int* in_sizes, int n_in,
                              void* d_out, int out_size)
{
    const float* Imodel   = (const float*)d_in[0];
    const float* Iobs     = (const float*)d_in[1];
    const float* metadata = (const float*)d_in[2];
    const void*  mask     = d_in[3];
    const float* W_img_in = (const float*)d_in[5];
    const float* b_img_in = (const float*)d_in[6];
    const float* W_img    = (const float*)d_in[7];
    const float* b_img    = (const float*)d_in[8];
    const float* W_lin_in = (const float*)d_in[9];
    const float* b_lin_in = (const float*)d_in[10];
    const float* W_mlp    = (const float*)d_in[11];
    const float* b_mlp    = (const float*)d_in[12];
    const float* W_out    = (const float*)d_in[13];
    const float* b_out    = (const float*)d_in[14];
    float* out = (float*)d_out;

    static int smem_set = 0;
    if (!smem_set) {
        cudaFuncSetAttribute(k_main, cudaFuncAttributeMaxDynamicSharedMemorySize,
                             SMEM_BYTES);
        smem_set = 1;
    }

    k_sc<<<16 + NCOMPB, 256>>>(mask, out);
    k_image<<<BB * (SS / RPB), ITB>>>(Imodel, Iobs, metadata, mask,
                                      W_img_in, b_img_in, W_img, b_img);
    k_main<<<NMAINB, MT_TPB, SMEM_BYTES>>>(metadata, W_lin_in, b_lin_in,
                                           W_mlp, b_mlp, W_out, b_out, out);
}